// round 1
// baseline (speedup 1.0000x reference)
#include <cuda_runtime.h>
#include <math.h>

#define BATCH 16
#define SEQ   4096
#define DIM   64
#define NH    8
#define NB    64      // n_buckets
#define NCHUNK 512    // chunks per batch (n_hashes * n_buckets)
#define SCALE 0.125f  // dim^-0.5

// ---- scratch (device globals; no runtime allocation) ----
__device__ unsigned char g_buckets[BATCH * NH * SEQ];          // 512 KB
__device__ int           g_st[BATCH * NH * SEQ];               // 2 MB  sorted slot -> original pos
__device__ float         g_o[(size_t)BATCH * NH * SEQ * DIM];  // 128 MB per-hash outputs (unsorted order)
__device__ float         g_lse[BATCH * NH * SEQ];              // 2 MB  per-hash logsumexp (unsorted order)

// ============================================================
// Kernel 1: LSH hashing. One thread per token; rotations in shared.
// ============================================================
extern "C" __global__ void __launch_bounds__(128)
hash_kernel(const float* __restrict__ qk, const float* __restrict__ rot)
{
    extern __shared__ float rot_s[];   // [64][256]  (f, h*32+i) -- same linear layout as input
    int tid = threadIdx.x;
    #pragma unroll
    for (int k = 0; k < 128; k++) rot_s[tid + k * 128] = rot[tid + k * 128];
    __syncthreads();

    int g = blockIdx.x * 128 + tid;          // token index in [0, BATCH*SEQ)
    int b = g >> 12, t = g & 4095;

    float q[64];
    const float4* qp = (const float4*)(qk + (size_t)g * 64);
    #pragma unroll
    for (int i = 0; i < 16; i++) {
        float4 x = qp[i];
        q[4*i] = x.x; q[4*i+1] = x.y; q[4*i+2] = x.z; q[4*i+3] = x.w;
    }

    for (int h = 0; h < NH; h++) {
        float acc[32];
        #pragma unroll
        for (int c = 0; c < 32; c++) acc[c] = 0.f;
        #pragma unroll 4
        for (int f = 0; f < 64; f++) {
            float qf = q[f];
            const float4* rp = (const float4*)(rot_s + f * 256 + h * 32);
            #pragma unroll
            for (int c4 = 0; c4 < 8; c4++) {
                float4 r4 = rp[c4];
                acc[c4*4+0] += qf * r4.x;
                acc[c4*4+1] += qf * r4.y;
                acc[c4*4+2] += qf * r4.z;
                acc[c4*4+3] += qf * r4.w;
            }
        }
        // argmax over concat([rotated, -rotated]) with first-occurrence tie rule
        float best = -1e30f; int bi = 0;
        #pragma unroll
        for (int c = 0; c < 32; c++) if (acc[c]  > best) { best = acc[c];  bi = c; }
        #pragma unroll
        for (int c = 0; c < 32; c++) if (-acc[c] > best) { best = -acc[c]; bi = 32 + c; }
        g_buckets[(b * NH + h) * SEQ + t] = (unsigned char)bi;
    }
}

// ============================================================
// Kernel 2: stable counting sort per (batch, hash). 128 blocks.
// ============================================================
extern "C" __global__ void __launch_bounds__(128)
sort_kernel()
{
    __shared__ int cnt[NB * 128];   // [bucket][thread]
    __shared__ int totals[NB];
    int tid = threadIdx.x;
    const unsigned char* bk = g_buckets + (size_t)blockIdx.x * SEQ;

    #pragma unroll
    for (int k = 0; k < NB; k++) cnt[k * 128 + tid] = 0;
    __syncthreads();

    int base = tid * 32;                      // 32 contiguous positions per thread
    #pragma unroll
    for (int p = 0; p < 32; p++) { int c = bk[base + p]; cnt[c * 128 + tid]++; }
    __syncthreads();

    if (tid < NB) {
        int s = 0;
        for (int u = 0; u < 128; u++) s += cnt[tid * 128 + u];
        totals[tid] = s;
    }
    __syncthreads();
    if (tid == 0) {
        int r = 0;
        for (int c = 0; c < NB; c++) { int x = totals[c]; totals[c] = r; r += x; }
    }
    __syncthreads();
    if (tid < NB) {
        int run = totals[tid];
        for (int u = 0; u < 128; u++) { int x = cnt[tid * 128 + u]; cnt[tid * 128 + u] = run; run += x; }
    }
    __syncthreads();

    int* st = g_st + (size_t)blockIdx.x * SEQ;
    #pragma unroll
    for (int p = 0; p < 32; p++) {
        int pos = base + p;
        int c = bk[pos];
        int s = cnt[c * 128 + tid]++;
        st[s] = pos;                            // positions ascend within bucket -> stable
    }
}

// ============================================================
// Kernel 3: chunked attention. One block per (chunk, batch).
// Shared layout (floats):
//   [0, 8320)      : union { K^T [64][129] (8256) ; P^T [128][65] (8320) }
//   [8320, 16512)  : V [128][64]
//   [16512,16640)  : inv-norm * scale per K column
//   [16640,16704)  : qpos (int)
//   [16704,16832)  : kpos (int)
// ============================================================
#define KT(f, j) s_kpT[(f) * 129 + (j)]
#define PT(j, r) s_kpT[(j) * 65 + (r)]

extern "C" __global__ void __launch_bounds__(256, 2)
attn_kernel(const float* __restrict__ qk, const float* __restrict__ v)
{
    extern __shared__ float sm[];
    float* s_kpT = sm;
    float* s_v   = sm + 8320;
    float* s_inv = sm + 16512;
    int*   s_qpos = (int*)(sm + 16640);
    int*   s_kpos = (int*)(sm + 16704);

    int tid = threadIdx.x;
    int c = blockIdx.x, b = blockIdx.y;
    int h  = c >> 6,  lc = c & 63;
    int pc = (c + NCHUNK - 1) & (NCHUNK - 1);   // jnp.roll(x,1,axis=1): prev chunk, wraps
    int hp = pc >> 6, lp = pc & 63;

    if (tid < 64) {
        int p = g_st[(b * NH + h) * SEQ + lc * 64 + tid];
        s_qpos[tid] = p; s_kpos[tid] = p;
    } else if (tid < 128) {
        int p = g_st[(b * NH + hp) * SEQ + lp * 64 + (tid - 64)];
        s_kpos[tid] = p;
    }
    __syncthreads();

    // gather K (raw qk rows, transposed) and V
    int w = tid >> 5, l = tid & 31;
    for (int j = w; j < 128; j += 8) {
        int p = s_kpos[j];
        const float* src = qk + ((size_t)b * SEQ + p) * DIM;
        KT(l, j)      = src[l];
        KT(l + 32, j) = src[l + 32];
        const float* vs = v + ((size_t)b * SEQ + p) * DIM;
        s_v[j * 64 + l]      = vs[l];
        s_v[j * 64 + l + 32] = vs[l + 32];
    }
    __syncthreads();

    if (tid < 128) {
        float ss = 0.f;
        #pragma unroll
        for (int f = 0; f < 64; f++) { float x = KT(f, tid); ss += x * x; }
        s_inv[tid] = SCALE / fmaxf(sqrtf(ss), 1e-12f);
    }
    __syncthreads();

    // dots: rows = ty + 16r (4), cols = tx + 16c (8)
    int ty = tid >> 4, tx = tid & 15;
    float acc[4][8];
    #pragma unroll
    for (int r = 0; r < 4; r++)
        #pragma unroll
        for (int cc = 0; cc < 8; cc++) acc[r][cc] = 0.f;

    #pragma unroll 4
    for (int f = 0; f < 64; f++) {
        float qv[4], kv[8];
        #pragma unroll
        for (int r = 0; r < 4; r++)  qv[r]  = KT(f, ty + 16 * r);
        #pragma unroll
        for (int cc = 0; cc < 8; cc++) kv[cc] = KT(f, tx + 16 * cc);
        #pragma unroll
        for (int r = 0; r < 4; r++)
            #pragma unroll
            for (int cc = 0; cc < 8; cc++) acc[r][cc] += qv[r] * kv[cc];
    }

    float invv[8]; int kp[8];
    #pragma unroll
    for (int cc = 0; cc < 8; cc++) { invv[cc] = s_inv[tx + 16 * cc]; kp[cc] = s_kpos[tx + 16 * cc]; }

    float lse_r[4]; int qp_r[4];
    #pragma unroll
    for (int r = 0; r < 4; r++) {
        int qp = s_qpos[ty + 16 * r]; qp_r[r] = qp;
        float mx = -1e30f;
        #pragma unroll
        for (int cc = 0; cc < 8; cc++) {
            float d = acc[r][cc] * invv[cc];
            if (kp[cc] == qp) d = -50000.f;      // self-attention mask
            acc[r][cc] = d;
            mx = fmaxf(mx, d);
        }
        #pragma unroll
        for (int o = 8; o >= 1; o >>= 1) mx = fmaxf(mx, __shfl_xor_sync(0xffffffffu, mx, o, 16));
        float s = 0.f;
        #pragma unroll
        for (int cc = 0; cc < 8; cc++) { float e = __expf(acc[r][cc] - mx); acc[r][cc] = e; s += e; }
        #pragma unroll
        for (int o = 8; o >= 1; o >>= 1) s += __shfl_xor_sync(0xffffffffu, s, o, 16);
        float rs = 1.f / s;
        #pragma unroll
        for (int cc = 0; cc < 8; cc++) acc[r][cc] *= rs;
        lse_r[r] = mx + logf(s);
    }
    __syncthreads();   // all K^T reads done; buffer reused for P^T

    #pragma unroll
    for (int r = 0; r < 4; r++) {
        #pragma unroll
        for (int cc = 0; cc < 8; cc++) PT(tx + 16 * cc, ty + 16 * r) = acc[r][cc];
        if (tx == 0) g_lse[(b * NH + h) * SEQ + qp_r[r]] = lse_r[r];
    }
    __syncthreads();

    // PV: rows = ty + 16r (4), cols = tx*4 + e (4 contiguous -> float4 store)
    float o4[4][4];
    #pragma unroll
    for (int r = 0; r < 4; r++)
        #pragma unroll
        for (int e = 0; e < 4; e++) o4[r][e] = 0.f;

    #pragma unroll 2
    for (int j = 0; j < 128; j++) {
        float pv[4];
        #pragma unroll
        for (int r = 0; r < 4; r++) pv[r] = PT(j, ty + 16 * r);
        float4 vv = *(const float4*)(s_v + j * 64 + tx * 4);
        #pragma unroll
        for (int r = 0; r < 4; r++) {
            o4[r][0] += pv[r] * vv.x;
            o4[r][1] += pv[r] * vv.y;
            o4[r][2] += pv[r] * vv.z;
            o4[r][3] += pv[r] * vv.w;
        }
    }

    float* outg = g_o + ((size_t)(b * NH + h) * SEQ) * DIM;
    #pragma unroll
    for (int r = 0; r < 4; r++) {
        float4 val = make_float4(o4[r][0], o4[r][1], o4[r][2], o4[r][3]);
        *(float4*)(outg + (size_t)qp_r[r] * DIM + tx * 4) = val;
    }
}

// ============================================================
// Kernel 4: combine hash rounds. One warp per token.
// ============================================================
extern "C" __global__ void __launch_bounds__(256)
combine_kernel(float* __restrict__ out)
{
    int wid = blockIdx.x * 8 + (threadIdx.x >> 5);
    int l = threadIdx.x & 31;
    int b = wid >> 12, t = wid & 4095;

    float lse[NH];
    #pragma unroll
    for (int h = 0; h < NH; h++) lse[h] = g_lse[(b * NH + h) * SEQ + t];
    float m = lse[0];
    #pragma unroll
    for (int h = 1; h < NH; h++) m = fmaxf(m, lse[h]);
    float Z = 0.f;
    #pragma unroll
    for (int h = 0; h < NH; h++) Z += __expf(lse[h] - m);
    float iz = 1.f / Z;

    float2 a = make_float2(0.f, 0.f);
    #pragma unroll
    for (int h = 0; h < NH; h++) {
        float wgt = __expf(lse[h] - m) * iz;
        const float2* row = (const float2*)(g_o + ((size_t)((b * NH + h) * SEQ) + t) * DIM);
        float2 x = row[l];
        a.x += wgt * x.x;
        a.y += wgt * x.y;
    }
    ((float2*)out)[((size_t)b * SEQ + t) * 32 + l] = a;
}

// ============================================================
extern "C" void kernel_launch(void* const* d_in, const int* in_sizes, int n_in,
                              void* d_out, int out_size)
{
    const float* qk  = (const float*)d_in[0];
    const float* v   = (const float*)d_in[1];
    const float* rot = (const float*)d_in[2];

    cudaFuncSetAttribute(hash_kernel, cudaFuncAttributeMaxDynamicSharedMemorySize, 65536);
    cudaFuncSetAttribute(attn_kernel, cudaFuncAttributeMaxDynamicSharedMemorySize, 67328);

    hash_kernel<<<(BATCH * SEQ) / 128, 128, 65536>>>(qk, rot);
    sort_kernel<<<BATCH * NH, 128>>>();
    attn_kernel<<<dim3(NCHUNK, BATCH), 256, 67328>>>(qk, v);
    combine_kernel<<<(BATCH * SEQ) / 8, 256>>>((float*)d_out);
}

// round 2
// speedup vs baseline: 1.0657x; 1.0657x over previous
#include <cuda_runtime.h>
#include <math.h>

#define BATCH 16
#define SEQ   4096
#define DIM   64
#define NH    8
#define NB    64
#define NCHUNK 512
#define SCALE 0.125f

// ---- packed f32x2 helpers (SASS FFMA2: 2x fp32 FMA throughput) ----
__device__ __forceinline__ unsigned long long pk2(float x, float y) {
    unsigned long long r; asm("mov.b64 %0, {%1,%2};" : "=l"(r) : "f"(x), "f"(y)); return r;
}
__device__ __forceinline__ float2 upk2(unsigned long long a) {
    float2 r; asm("mov.b64 {%0,%1}, %2;" : "=f"(r.x), "=f"(r.y) : "l"(a)); return r;
}
#define FFMA2(d, a, b) asm("fma.rn.f32x2 %0, %1, %2, %0;" : "+l"(d) : "l"(a), "l"(b))

// ---- scratch ----
__device__ unsigned char g_buckets[BATCH * NH * SEQ];
__device__ int           g_st[BATCH * NH * SEQ];
__device__ float         g_o[(size_t)BATCH * NH * SEQ * DIM];
__device__ float         g_lse[BATCH * NH * SEQ];

// ============================================================
// Kernel 1: LSH hashing (FFMA2 inner product)
// ============================================================
extern "C" __global__ void __launch_bounds__(128)
hash_kernel(const float* __restrict__ qk, const float* __restrict__ rot)
{
    extern __shared__ float rot_s[];   // [64][256]
    int tid = threadIdx.x;
    #pragma unroll
    for (int k = 0; k < 128; k++) rot_s[tid + k * 128] = rot[tid + k * 128];
    __syncthreads();

    int g = blockIdx.x * 128 + tid;
    int b = g >> 12, t = g & 4095;

    float q[64];
    const float4* qp = (const float4*)(qk + (size_t)g * 64);
    #pragma unroll
    for (int i = 0; i < 16; i++) {
        float4 x = qp[i];
        q[4*i] = x.x; q[4*i+1] = x.y; q[4*i+2] = x.z; q[4*i+3] = x.w;
    }

    for (int h = 0; h < NH; h++) {
        unsigned long long acc2[16];
        #pragma unroll
        for (int c = 0; c < 16; c++) acc2[c] = 0ull;
        #pragma unroll 4
        for (int f = 0; f < 64; f++) {
            unsigned long long q2 = pk2(q[f], q[f]);
            const ulonglong2* rp = (const ulonglong2*)(rot_s + f * 256 + h * 32);
            #pragma unroll
            for (int c4 = 0; c4 < 8; c4++) {
                ulonglong2 r2 = rp[c4];
                FFMA2(acc2[c4*2],   q2, r2.x);
                FFMA2(acc2[c4*2+1], q2, r2.y);
            }
        }
        float best = -1e30f; int bi = 0;
        #pragma unroll
        for (int c = 0; c < 16; c++) {
            float2 d = upk2(acc2[c]);
            if (d.x > best) { best = d.x; bi = 2*c; }
            if (d.y > best) { best = d.y; bi = 2*c+1; }
        }
        #pragma unroll
        for (int c = 0; c < 16; c++) {
            float2 d = upk2(acc2[c]);
            if (-d.x > best) { best = -d.x; bi = 32 + 2*c; }
            if (-d.y > best) { best = -d.y; bi = 32 + 2*c+1; }
        }
        g_buckets[(b * NH + h) * SEQ + t] = (unsigned char)bi;
    }
}

// ============================================================
// Kernel 2: stable counting sort per (batch, hash)
// ============================================================
extern "C" __global__ void __launch_bounds__(128)
sort_kernel()
{
    __shared__ int cnt[NB * 128];
    __shared__ int totals[NB];
    int tid = threadIdx.x;
    const unsigned char* bk = g_buckets + (size_t)blockIdx.x * SEQ;

    #pragma unroll
    for (int k = 0; k < NB; k++) cnt[k * 128 + tid] = 0;
    __syncthreads();

    int base = tid * 32;
    #pragma unroll
    for (int p = 0; p < 32; p++) { int c = bk[base + p]; cnt[c * 128 + tid]++; }
    __syncthreads();

    if (tid < NB) {
        int s = 0;
        for (int u = 0; u < 128; u++) s += cnt[tid * 128 + u];
        totals[tid] = s;
    }
    __syncthreads();
    if (tid == 0) {
        int r = 0;
        for (int c = 0; c < NB; c++) { int x = totals[c]; totals[c] = r; r += x; }
    }
    __syncthreads();
    if (tid < NB) {
        int run = totals[tid];
        for (int u = 0; u < 128; u++) { int x = cnt[tid * 128 + u]; cnt[tid * 128 + u] = run; run += x; }
    }
    __syncthreads();

    int* st = g_st + (size_t)blockIdx.x * SEQ;
    #pragma unroll
    for (int p = 0; p < 32; p++) {
        int pos = base + p;
        int c = bk[pos];
        int s = cnt[c * 128 + tid]++;
        st[s] = pos;
    }
}

// ============================================================
// Kernel 3: chunked attention with FFMA2 GEMMs
// Shared layout (floats):
//   [0, 8320)      : union { K^T [64][130] ; P^T [128][65] }
//   [8320, 16512)  : V [128][64]
//   [16512,16640)  : inv-norm * scale per K column
//   [16640,16704)  : qpos (int)
//   [16704,16832)  : kpos (int)
// ============================================================
#define KT(f, j) s_kpT[(f) * 130 + (j)]
#define PT(j, r) s_kpT[(j) * 65 + (r)]

extern "C" __global__ void __launch_bounds__(256, 2)
attn_kernel(const float* __restrict__ qk, const float* __restrict__ v)
{
    extern __shared__ float sm[];
    float* s_kpT = sm;
    float* s_v   = sm + 8320;
    float* s_inv = sm + 16512;
    int*   s_qpos = (int*)(sm + 16640);
    int*   s_kpos = (int*)(sm + 16704);

    int tid = threadIdx.x;
    int c = blockIdx.x, b = blockIdx.y;
    int h  = c >> 6,  lc = c & 63;
    int pc = (c + NCHUNK - 1) & (NCHUNK - 1);
    int hp = pc >> 6, lp = pc & 63;

    if (tid < 64) {
        int p = g_st[(b * NH + h) * SEQ + lc * 64 + tid];
        s_qpos[tid] = p; s_kpos[tid] = p;
    } else if (tid < 128) {
        int p = g_st[(b * NH + hp) * SEQ + lp * 64 + (tid - 64)];
        s_kpos[tid] = p;
    }
    __syncthreads();

    int w = tid >> 5, l = tid & 31;
    for (int j = w; j < 128; j += 8) {
        int p = s_kpos[j];
        const float* src = qk + ((size_t)b * SEQ + p) * DIM;
        KT(l, j)      = src[l];
        KT(l + 32, j) = src[l + 32];
        const float* vs = v + ((size_t)b * SEQ + p) * DIM;
        s_v[j * 64 + l]      = vs[l];
        s_v[j * 64 + l + 32] = vs[l + 32];
    }
    __syncthreads();

    if (tid < 128) {
        float ss = 0.f;
        #pragma unroll
        for (int f = 0; f < 64; f++) { float x = KT(f, tid); ss += x * x; }
        s_inv[tid] = SCALE / fmaxf(sqrtf(ss), 1e-12f);
    }
    __syncthreads();

    // dots: rows = ty + 16r (4), cols = 2*tx + 32*c2 + {0,1} (8)
    int ty = tid >> 4, tx = tid & 15;
    unsigned long long acc2[4][4];
    #pragma unroll
    for (int r = 0; r < 4; r++)
        #pragma unroll
        for (int c2 = 0; c2 < 4; c2++) acc2[r][c2] = 0ull;

    #pragma unroll 2
    for (int f = 0; f < 64; f++) {
        unsigned long long kv2[4];
        #pragma unroll
        for (int c2 = 0; c2 < 4; c2++)
            kv2[c2] = *(const unsigned long long*)&KT(f, 2 * tx + 32 * c2);
        #pragma unroll
        for (int r = 0; r < 4; r++) {
            float qf = KT(f, ty + 16 * r);
            unsigned long long q2 = pk2(qf, qf);
            #pragma unroll
            for (int c2 = 0; c2 < 4; c2++) FFMA2(acc2[r][c2], q2, kv2[c2]);
        }
    }

    float2 invv[4]; int2 kp2[4];
    #pragma unroll
    for (int c2 = 0; c2 < 4; c2++) {
        invv[c2] = *(const float2*)&s_inv[2 * tx + 32 * c2];
        kp2[c2]  = *(const int2*)&s_kpos[2 * tx + 32 * c2];
    }

    float pr[4][8];
    float lse_r[4]; int qp_r[4];
    #pragma unroll
    for (int r = 0; r < 4; r++) {
        int qp = s_qpos[ty + 16 * r]; qp_r[r] = qp;
        float mx = -1e30f;
        #pragma unroll
        for (int c2 = 0; c2 < 4; c2++) {
            float2 d = upk2(acc2[r][c2]);
            float dx = d.x * invv[c2].x;
            float dy = d.y * invv[c2].y;
            if (kp2[c2].x == qp) dx = -50000.f;
            if (kp2[c2].y == qp) dy = -50000.f;
            pr[r][2*c2]   = dx;
            pr[r][2*c2+1] = dy;
            mx = fmaxf(mx, fmaxf(dx, dy));
        }
        #pragma unroll
        for (int o = 8; o >= 1; o >>= 1) mx = fmaxf(mx, __shfl_xor_sync(0xffffffffu, mx, o, 16));
        float s = 0.f;
        #pragma unroll
        for (int cc = 0; cc < 8; cc++) { float e = __expf(pr[r][cc] - mx); pr[r][cc] = e; s += e; }
        #pragma unroll
        for (int o = 8; o >= 1; o >>= 1) s += __shfl_xor_sync(0xffffffffu, s, o, 16);
        float rs = 1.f / s;
        #pragma unroll
        for (int cc = 0; cc < 8; cc++) pr[r][cc] *= rs;
        lse_r[r] = mx + logf(s);
    }
    __syncthreads();   // KT reads done; buffer reused as P^T

    #pragma unroll
    for (int r = 0; r < 4; r++) {
        #pragma unroll
        for (int c2 = 0; c2 < 4; c2++) {
            PT(2 * tx + 32 * c2,     ty + 16 * r) = pr[r][2*c2];
            PT(2 * tx + 32 * c2 + 1, ty + 16 * r) = pr[r][2*c2+1];
        }
        if (tx == 0) g_lse[(b * NH + h) * SEQ + qp_r[r]] = lse_r[r];
    }
    __syncthreads();

    // PV: rows = ty + 16r, cols = tx*4 + {0..3}
    unsigned long long o2[4][2];
    #pragma unroll
    for (int r = 0; r < 4; r++) { o2[r][0] = 0ull; o2[r][1] = 0ull; }

    #pragma unroll 2
    for (int j = 0; j < 128; j++) {
        ulonglong2 vv = *(const ulonglong2*)(s_v + j * 64 + tx * 4);
        #pragma unroll
        for (int r = 0; r < 4; r++) {
            float pv = PT(j, ty + 16 * r);
            unsigned long long p2 = pk2(pv, pv);
            FFMA2(o2[r][0], p2, vv.x);
            FFMA2(o2[r][1], p2, vv.y);
        }
    }

    float* outg = g_o + ((size_t)(b * NH + h) * SEQ) * DIM;
    #pragma unroll
    for (int r = 0; r < 4; r++) {
        float2 a = upk2(o2[r][0]);
        float2 bb = upk2(o2[r][1]);
        float4 val = make_float4(a.x, a.y, bb.x, bb.y);
        *(float4*)(outg + (size_t)qp_r[r] * DIM + tx * 4) = val;
    }
}

// ============================================================
// Kernel 4: combine hash rounds
// ============================================================
extern "C" __global__ void __launch_bounds__(256)
combine_kernel(float* __restrict__ out)
{
    int wid = blockIdx.x * 8 + (threadIdx.x >> 5);
    int l = threadIdx.x & 31;
    int b = wid >> 12, t = wid & 4095;

    float lse[NH];
    #pragma unroll
    for (int h = 0; h < NH; h++) lse[h] = g_lse[(b * NH + h) * SEQ + t];
    float m = lse[0];
    #pragma unroll
    for (int h = 1; h < NH; h++) m = fmaxf(m, lse[h]);
    float Z = 0.f;
    #pragma unroll
    for (int h = 0; h < NH; h++) Z += __expf(lse[h] - m);
    float iz = 1.f / Z;

    float2 a = make_float2(0.f, 0.f);
    #pragma unroll
    for (int h = 0; h < NH; h++) {
        float wgt = __expf(lse[h] - m) * iz;
        const float2* row = (const float2*)(g_o + ((size_t)((b * NH + h) * SEQ) + t) * DIM);
        float2 x = row[l];
        a.x += wgt * x.x;
        a.y += wgt * x.y;
    }
    ((float2*)out)[((size_t)b * SEQ + t) * 32 + l] = a;
}

// ============================================================
extern "C" void kernel_launch(void* const* d_in, const int* in_sizes, int n_in,
                              void* d_out, int out_size)
{
    const float* qk  = (const float*)d_in[0];
    const float* v   = (const float*)d_in[1];
    const float* rot = (const float*)d_in[2];

    cudaFuncSetAttribute(hash_kernel, cudaFuncAttributeMaxDynamicSharedMemorySize, 65536);
    cudaFuncSetAttribute(attn_kernel, cudaFuncAttributeMaxDynamicSharedMemorySize, 67328);

    hash_kernel<<<(BATCH * SEQ) / 128, 128, 65536>>>(qk, rot);
    sort_kernel<<<BATCH * NH, 128>>>();
    attn_kernel<<<dim3(NCHUNK, BATCH), 256, 67328>>>(qk, v);
    combine_kernel<<<(BATCH * SEQ) / 8, 256>>>((float*)d_out);
}

// round 4
// speedup vs baseline: 1.4194x; 1.3319x over previous
#include <cuda_runtime.h>
#include <math.h>
#include <stdint.h>

#define BATCH 16
#define SEQ   4096
#define DIM   64
#define NH    8
#define NB    64
#define NCHUNK 512
#define SCALE 0.125f

// ---- tf32 mma.sync helpers (baseline PTX, works on compute_103) ----
__device__ __forceinline__ uint32_t cvt_tf32(float x) {
    uint32_t r; asm("cvt.rna.tf32.f32 %0, %1;" : "=r"(r) : "f"(x)); return r;
}
__device__ __forceinline__ void mma_tf32(float* c, uint32_t a0, uint32_t a1, uint32_t a2, uint32_t a3,
                                         uint32_t b0, uint32_t b1) {
    asm volatile("mma.sync.aligned.m16n8k8.row.col.f32.tf32.tf32.f32 "
                 "{%0,%1,%2,%3}, {%4,%5,%6,%7}, {%8,%9}, {%0,%1,%2,%3};"
                 : "+f"(c[0]), "+f"(c[1]), "+f"(c[2]), "+f"(c[3])
                 : "r"(a0), "r"(a1), "r"(a2), "r"(a3), "r"(b0), "r"(b1));
}

// ---- packed f32x2 for hash kernel ----
__device__ __forceinline__ unsigned long long pk2(float x, float y) {
    unsigned long long r; asm("mov.b64 %0, {%1,%2};" : "=l"(r) : "f"(x), "f"(y)); return r;
}
__device__ __forceinline__ float2 upk2(unsigned long long a) {
    float2 r; asm("mov.b64 {%0,%1}, %2;" : "=f"(r.x), "=f"(r.y) : "l"(a)); return r;
}
#define FFMA2(d, a, b) asm("fma.rn.f32x2 %0, %1, %2, %0;" : "+l"(d) : "l"(a), "l"(b))

// ---- scratch ----
__device__ unsigned char g_buckets[BATCH * NH * SEQ];
__device__ int           g_st[BATCH * NH * SEQ];
__device__ float         g_o[(size_t)BATCH * NH * SEQ * DIM];
__device__ float         g_lse[BATCH * NH * SEQ];

// ============================================================
// Kernel 1: LSH hashing (FFMA2)
// ============================================================
extern "C" __global__ void __launch_bounds__(128)
hash_kernel(const float* __restrict__ qk, const float* __restrict__ rot)
{
    extern __shared__ float rot_s[];
    int tid = threadIdx.x;
    #pragma unroll
    for (int k = 0; k < 128; k++) rot_s[tid + k * 128] = rot[tid + k * 128];
    __syncthreads();

    int g = blockIdx.x * 128 + tid;
    int b = g >> 12, t = g & 4095;

    float q[64];
    const float4* qp = (const float4*)(qk + (size_t)g * 64);
    #pragma unroll
    for (int i = 0; i < 16; i++) {
        float4 x = qp[i];
        q[4*i] = x.x; q[4*i+1] = x.y; q[4*i+2] = x.z; q[4*i+3] = x.w;
    }

    for (int h = 0; h < NH; h++) {
        unsigned long long acc2[16];
        #pragma unroll
        for (int c = 0; c < 16; c++) acc2[c] = 0ull;
        #pragma unroll 4
        for (int f = 0; f < 64; f++) {
            unsigned long long q2 = pk2(q[f], q[f]);
            const ulonglong2* rp = (const ulonglong2*)(rot_s + f * 256 + h * 32);
            #pragma unroll
            for (int c4 = 0; c4 < 8; c4++) {
                ulonglong2 r2 = rp[c4];
                FFMA2(acc2[c4*2],   q2, r2.x);
                FFMA2(acc2[c4*2+1], q2, r2.y);
            }
        }
        float best = -1e30f; int bi = 0;
        #pragma unroll
        for (int c = 0; c < 16; c++) {
            float2 d = upk2(acc2[c]);
            if (d.x > best) { best = d.x; bi = 2*c; }
            if (d.y > best) { best = d.y; bi = 2*c+1; }
        }
        #pragma unroll
        for (int c = 0; c < 16; c++) {
            float2 d = upk2(acc2[c]);
            if (-d.x > best) { best = -d.x; bi = 32 + 2*c; }
            if (-d.y > best) { best = -d.y; bi = 32 + 2*c+1; }
        }
        g_buckets[(b * NH + h) * SEQ + t] = (unsigned char)bi;
    }
}

// ============================================================
// Kernel 2: stable counting sort per (batch, hash)
// ============================================================
extern "C" __global__ void __launch_bounds__(128)
sort_kernel()
{
    __shared__ int cnt[NB * 128];
    __shared__ int totals[NB];
    int tid = threadIdx.x;
    const unsigned char* bk = g_buckets + (size_t)blockIdx.x * SEQ;

    #pragma unroll
    for (int k = 0; k < NB; k++) cnt[k * 128 + tid] = 0;
    __syncthreads();

    int base = tid * 32;
    #pragma unroll
    for (int p = 0; p < 32; p++) { int c = bk[base + p]; cnt[c * 128 + tid]++; }
    __syncthreads();

    if (tid < NB) {
        int s = 0;
        for (int u = 0; u < 128; u++) s += cnt[tid * 128 + u];
        totals[tid] = s;
    }
    __syncthreads();
    if (tid == 0) {
        int r = 0;
        for (int c = 0; c < NB; c++) { int x = totals[c]; totals[c] = r; r += x; }
    }
    __syncthreads();
    if (tid < NB) {
        int run = totals[tid];
        for (int u = 0; u < 128; u++) { int x = cnt[tid * 128 + u]; cnt[tid * 128 + u] = run; run += x; }
    }
    __syncthreads();

    int* st = g_st + (size_t)blockIdx.x * SEQ;
    #pragma unroll
    for (int p = 0; p < 32; p++) {
        int pos = base + p;
        int c = bk[pos];
        int s = cnt[c * 128 + tid]++;
        st[s] = pos;
    }
}

// ============================================================
// Kernel 3: attention via tf32 mma.sync. Block = (chunk, batch), 8 warps.
// Warp w: m-stripe (w&3)*16 Q-rows, n-half (w>>2).
// SMEM (bytes):
//   [0, 34816)      K tile [128 keys][68 pad] tf32 bits  (union: P [64][132])
//   [34816, 68608)  V^T [64 dims][132 pad] tf32 bits
//   [68608, 69120)  inv[128]
//   [69120, 69632)  kpos[128]
//   [69632, 70144)  red[2][64]
// ============================================================
#define KPAD 68
#define VPAD 132
#define PPAD 132
#define SM_VT   34816
#define SM_INV  68608
#define SM_KPOS 69120
#define SM_RED  69632
#define SM_TOTAL 70144

extern "C" __global__ void __launch_bounds__(256)
attn_kernel(const float* __restrict__ qk, const float* __restrict__ v)
{
    extern __shared__ char smem[];
    uint32_t* s_ku  = (uint32_t*)smem;
    uint32_t* s_vtu = (uint32_t*)(smem + SM_VT);
    uint32_t* s_pu  = (uint32_t*)smem;        // overlays K tile
    float*    s_inv = (float*)(smem + SM_INV);
    int*      s_kpos = (int*)(smem + SM_KPOS);
    float*    s_red = (float*)(smem + SM_RED);

    int tid = threadIdx.x;
    int w = tid >> 5, l = tid & 31;
    int c = blockIdx.x, b = blockIdx.y;
    int h = c >> 6;
    int pc = (c + NCHUNK - 1) & (NCHUNK - 1);

    if (tid < 128) {
        int sel = tid >> 6;                    // 0 = prev chunk, 1 = cur chunk
        int ch = sel ? c : pc;
        s_kpos[tid] = g_st[(b * NH + (ch >> 6)) * SEQ + (ch & 63) * 64 + (tid & 63)];
    }
    __syncthreads();

    // gather: K rows (tf32-rounded) + norms, V^T (tf32-rounded)
    #pragma unroll 1
    for (int it = 0; it < 16; it++) {
        int j = w * 16 + it;
        int p = s_kpos[j];
        const float2* src = (const float2*)(qk + ((size_t)b * SEQ + p) * DIM);
        float2 x = src[l];
        uint32_t* kr = s_ku + j * KPAD;
        kr[2 * l]     = cvt_tf32(x.x);
        kr[2 * l + 1] = cvt_tf32(x.y);
        float ss = x.x * x.x + x.y * x.y;
        #pragma unroll
        for (int o = 16; o >= 1; o >>= 1) ss += __shfl_xor_sync(0xffffffffu, ss, o);
        if (l == 0) s_inv[j] = SCALE / fmaxf(sqrtf(ss), 1e-12f);
        const float* vs = v + ((size_t)b * SEQ + p) * DIM;
        s_vtu[l * VPAD + j]        = cvt_tf32(vs[l]);
        s_vtu[(l + 32) * VPAD + j] = cvt_tf32(vs[l + 32]);
    }
    __syncthreads();

    int r = l >> 2, q = l & 3;
    int m0 = (w & 3) * 16, nh = w >> 2, n0 = nh * 64;

    // GEMM1: S[16 rows x 64 cols per warp] = Q . K^T  (tf32 mma)
    float acc[8][4];
    #pragma unroll
    for (int j = 0; j < 8; j++)
        #pragma unroll
        for (int k = 0; k < 4; k++) acc[j][k] = 0.f;

    #pragma unroll
    for (int s = 0; s < 8; s++) {
        const uint32_t* A1 = s_ku + (64 + m0 + r) * KPAD + 8 * s + q;
        const uint32_t* A2 = s_ku + (64 + m0 + 8 + r) * KPAD + 8 * s + q;
        uint32_t a0 = A1[0], a1 = A2[0], a2 = A1[4], a3 = A2[4];
        #pragma unroll
        for (int j = 0; j < 8; j++) {
            const uint32_t* B = s_ku + (n0 + 8 * j + r) * KPAD + 8 * s + q;
            mma_tf32(acc[j], a0, a1, a2, a3, B[0], B[4]);
        }
    }

    // softmax epilogue (no max-subtraction; dots ~N(0,1))
    int row1 = m0 + r, row2 = row1 + 8;
    int qp1 = s_kpos[64 + row1], qp2 = s_kpos[64 + row2];
    float sum1 = 0.f, sum2 = 0.f;
    #pragma unroll
    for (int j = 0; j < 8; j++) {
        int col0 = n0 + 8 * j + 2 * q, col1 = col0 + 1;
        float i0 = s_inv[col0], i1 = s_inv[col1];
        int k0 = s_kpos[col0], k1 = s_kpos[col1];
        float e;
        e = (k0 == qp1) ? 0.f : __expf(acc[j][0] * i0); acc[j][0] = e; sum1 += e;
        e = (k1 == qp1) ? 0.f : __expf(acc[j][1] * i1); acc[j][1] = e; sum1 += e;
        e = (k0 == qp2) ? 0.f : __expf(acc[j][2] * i0); acc[j][2] = e; sum2 += e;
        e = (k1 == qp2) ? 0.f : __expf(acc[j][3] * i1); acc[j][3] = e; sum2 += e;
    }
    sum1 += __shfl_xor_sync(0xffffffffu, sum1, 1);
    sum1 += __shfl_xor_sync(0xffffffffu, sum1, 2);
    sum2 += __shfl_xor_sync(0xffffffffu, sum2, 1);
    sum2 += __shfl_xor_sync(0xffffffffu, sum2, 2);
    if (q == 0) { s_red[nh * 64 + row1] = sum1; s_red[nh * 64 + row2] = sum2; }
    __syncthreads();          // all GEMM1 K-tile reads complete

    // store P (tf32 bits) over the K tile
    #pragma unroll
    for (int j = 0; j < 8; j++) {
        int col0 = n0 + 8 * j + 2 * q;
        s_pu[row1 * PPAD + col0]     = cvt_tf32(acc[j][0]);
        s_pu[row1 * PPAD + col0 + 1] = cvt_tf32(acc[j][1]);
        s_pu[row2 * PPAD + col0]     = cvt_tf32(acc[j][2]);
        s_pu[row2 * PPAD + col0 + 1] = cvt_tf32(acc[j][3]);
    }
    __syncthreads();

    // GEMM2: O[16 x 32 per warp] = P . V
    float o2[4][4];
    #pragma unroll
    for (int j = 0; j < 4; j++)
        #pragma unroll
        for (int k = 0; k < 4; k++) o2[j][k] = 0.f;

    #pragma unroll
    for (int s = 0; s < 16; s++) {
        const uint32_t* A1 = s_pu + (m0 + r) * PPAD + 8 * s + q;
        const uint32_t* A2 = s_pu + (m0 + 8 + r) * PPAD + 8 * s + q;
        uint32_t a0 = A1[0], a1 = A2[0], a2 = A1[4], a3 = A2[4];
        #pragma unroll
        for (int j = 0; j < 4; j++) {
            const uint32_t* B = s_vtu + (nh * 32 + 8 * j + r) * VPAD + 8 * s + q;
            mma_tf32(o2[j], a0, a1, a2, a3, B[0], B[4]);
        }
    }

    float t1 = s_red[row1] + s_red[64 + row1];
    float t2 = s_red[row2] + s_red[64 + row2];
    float is1 = 1.f / t1, is2 = 1.f / t2;
    size_t obase = (size_t)(b * NH + h) * SEQ;
    if (nh == 0 && q == 0) {
        g_lse[obase + qp1] = logf(t1);
        g_lse[obase + qp2] = logf(t2);
    }
    float* og1 = g_o + (obase + qp1) * DIM;
    float* og2 = g_o + (obase + qp2) * DIM;
    #pragma unroll
    for (int j = 0; j < 4; j++) {
        int d = nh * 32 + 8 * j + 2 * q;
        *(float2*)(og1 + d) = make_float2(o2[j][0] * is1, o2[j][1] * is1);
        *(float2*)(og2 + d) = make_float2(o2[j][2] * is2, o2[j][3] * is2);
    }
}

// ============================================================
// Kernel 4: combine hash rounds
// ============================================================
extern "C" __global__ void __launch_bounds__(256)
combine_kernel(float* __restrict__ out)
{
    int wid = blockIdx.x * 8 + (threadIdx.x >> 5);
    int l = threadIdx.x & 31;
    int b = wid >> 12, t = wid & 4095;

    float lse[NH];
    #pragma unroll
    for (int h = 0; h < NH; h++) lse[h] = g_lse[(b * NH + h) * SEQ + t];
    float m = lse[0];
    #pragma unroll
    for (int h = 1; h < NH; h++) m = fmaxf(m, lse[h]);
    float Z = 0.f;
    #pragma unroll
    for (int h = 0; h < NH; h++) Z += __expf(lse[h] - m);
    float iz = 1.f / Z;

    float2 a = make_float2(0.f, 0.f);
    #pragma unroll
    for (int h = 0; h < NH; h++) {
        float wgt = __expf(lse[h] - m) * iz;
        const float2* row = (const float2*)(g_o + ((size_t)((b * NH + h) * SEQ) + t) * DIM);
        float2 x = row[l];
        a.x += wgt * x.x;
        a.y += wgt * x.y;
    }
    ((float2*)out)[((size_t)b * SEQ + t) * 32 + l] = a;
}

// ============================================================
extern "C" void kernel_launch(void* const* d_in, const int* in_sizes, int n_in,
                              void* d_out, int out_size)
{
    const float* qk  = (const float*)d_in[0];
    const float* v   = (const float*)d_in[1];
    const float* rot = (const float*)d_in[2];

    cudaFuncSetAttribute(hash_kernel, cudaFuncAttributeMaxDynamicSharedMemorySize, 65536);
    cudaFuncSetAttribute(attn_kernel, cudaFuncAttributeMaxDynamicSharedMemorySize, SM_TOTAL);

    hash_kernel<<<(BATCH * SEQ) / 128, 128, 65536>>>(qk, rot);
    sort_kernel<<<BATCH * NH, 128>>>();
    attn_kernel<<<dim3(NCHUNK, BATCH), 256, SM_TOTAL>>>(qk, v);
    combine_kernel<<<(BATCH * SEQ) / 8, 256>>>((float*)d_out);
}

// round 5
// speedup vs baseline: 1.8352x; 1.2929x over previous
#include <cuda_runtime.h>
#include <cuda_fp16.h>
#include <math.h>
#include <stdint.h>

#define BATCH 16
#define SEQ   4096
#define DIM   64
#define NH    8
#define NB    64
#define NCHUNK 512
#define SCALE 0.125f

// ---- fp16 mma.sync m16n8k16 (baseline PTX, works on compute_103) ----
__device__ __forceinline__ void mma_f16(float* c, uint32_t a0, uint32_t a1, uint32_t a2, uint32_t a3,
                                        uint32_t b0, uint32_t b1) {
    asm volatile("mma.sync.aligned.m16n8k16.row.col.f32.f16.f16.f32 "
                 "{%0,%1,%2,%3}, {%4,%5,%6,%7}, {%8,%9}, {%0,%1,%2,%3};"
                 : "+f"(c[0]), "+f"(c[1]), "+f"(c[2]), "+f"(c[3])
                 : "r"(a0), "r"(a1), "r"(a2), "r"(a3), "r"(b0), "r"(b1));
}
// interleave: within each 8-word group put logical words (q, q+4) adjacent at (2q, 2q+1)
__device__ __forceinline__ int ilv(int w) {
    return (w & ~7) | ((w & 3) << 1) | ((w >> 2) & 1);
}

// ---- packed f32x2 for hash kernel ----
__device__ __forceinline__ unsigned long long pk2(float x, float y) {
    unsigned long long r; asm("mov.b64 %0, {%1,%2};" : "=l"(r) : "f"(x), "f"(y)); return r;
}
__device__ __forceinline__ float2 upk2(unsigned long long a) {
    float2 r; asm("mov.b64 {%0,%1}, %2;" : "=f"(r.x), "=f"(r.y) : "l"(a)); return r;
}
#define FFMA2(d, a, b) asm("fma.rn.f32x2 %0, %1, %2, %0;" : "+l"(d) : "l"(a), "l"(b))

// ---- scratch ----
__device__ unsigned char g_buckets[BATCH * NH * SEQ];
__device__ int           g_st[BATCH * NH * SEQ];
__device__ __half        g_oh[(size_t)BATCH * NH * SEQ * DIM];   // 64 MB fp16 per-hash outputs
__device__ float         g_lse[BATCH * NH * SEQ];

// ============================================================
// Kernel 1: LSH hashing (FFMA2)
// ============================================================
extern "C" __global__ void __launch_bounds__(128)
hash_kernel(const float* __restrict__ qk, const float* __restrict__ rot)
{
    extern __shared__ float rot_s[];
    int tid = threadIdx.x;
    #pragma unroll
    for (int k = 0; k < 128; k++) rot_s[tid + k * 128] = rot[tid + k * 128];
    __syncthreads();

    int g = blockIdx.x * 128 + tid;
    int b = g >> 12, t = g & 4095;

    float q[64];
    const float4* qp = (const float4*)(qk + (size_t)g * 64);
    #pragma unroll
    for (int i = 0; i < 16; i++) {
        float4 x = qp[i];
        q[4*i] = x.x; q[4*i+1] = x.y; q[4*i+2] = x.z; q[4*i+3] = x.w;
    }

    for (int h = 0; h < NH; h++) {
        unsigned long long acc2[16];
        #pragma unroll
        for (int c = 0; c < 16; c++) acc2[c] = 0ull;
        #pragma unroll 4
        for (int f = 0; f < 64; f++) {
            unsigned long long q2 = pk2(q[f], q[f]);
            const ulonglong2* rp = (const ulonglong2*)(rot_s + f * 256 + h * 32);
            #pragma unroll
            for (int c4 = 0; c4 < 8; c4++) {
                ulonglong2 r2 = rp[c4];
                FFMA2(acc2[c4*2],   q2, r2.x);
                FFMA2(acc2[c4*2+1], q2, r2.y);
            }
        }
        float best = -1e30f; int bi = 0;
        #pragma unroll
        for (int c = 0; c < 16; c++) {
            float2 d = upk2(acc2[c]);
            if (d.x > best) { best = d.x; bi = 2*c; }
            if (d.y > best) { best = d.y; bi = 2*c+1; }
        }
        #pragma unroll
        for (int c = 0; c < 16; c++) {
            float2 d = upk2(acc2[c]);
            if (-d.x > best) { best = -d.x; bi = 32 + 2*c; }
            if (-d.y > best) { best = -d.y; bi = 32 + 2*c+1; }
        }
        g_buckets[(b * NH + h) * SEQ + t] = (unsigned char)bi;
    }
}

// ============================================================
// Kernel 2: stable counting sort per (batch, hash)
// ============================================================
extern "C" __global__ void __launch_bounds__(128)
sort_kernel()
{
    __shared__ int cnt[NB * 128];
    __shared__ int totals[NB];
    int tid = threadIdx.x;
    const unsigned char* bk = g_buckets + (size_t)blockIdx.x * SEQ;

    #pragma unroll
    for (int k = 0; k < NB; k++) cnt[k * 128 + tid] = 0;
    __syncthreads();

    int base = tid * 32;
    #pragma unroll
    for (int p = 0; p < 32; p++) { int c = bk[base + p]; cnt[c * 128 + tid]++; }
    __syncthreads();

    if (tid < NB) {
        int s = 0;
        for (int u = 0; u < 128; u++) s += cnt[tid * 128 + u];
        totals[tid] = s;
    }
    __syncthreads();
    if (tid == 0) {
        int r = 0;
        for (int c = 0; c < NB; c++) { int x = totals[c]; totals[c] = r; r += x; }
    }
    __syncthreads();
    if (tid < NB) {
        int run = totals[tid];
        for (int u = 0; u < 128; u++) { int x = cnt[tid * 128 + u]; cnt[tid * 128 + u] = run; run += x; }
    }
    __syncthreads();

    int* st = g_st + (size_t)blockIdx.x * SEQ;
    #pragma unroll
    for (int p = 0; p < 32; p++) {
        int pos = base + p;
        int c = bk[pos];
        int s = cnt[c * 128 + tid]++;
        st[s] = pos;
    }
}

// ============================================================
// Kernel 3: fp16 mma attention. Block = (chunk, batch), 8 warps, 3 CTA/SM.
// Word layouts (1 word = half2 = 2 fp16):
//   K tile : 128 rows x 40-word stride (logical 32 words = 64 feats), interleaved
//   P tile : 64 rows x 74-word stride (logical 64 words = 128 keys), overlays K
//   V^T    : 64 dim-rows x 74-word stride (logical 64 words = 128 keys)
// SMEM bytes:
//   [0, 20480)      K tile / P tile
//   [20480, 39424)  V^T
//   [39424, 39936)  inv[128]
//   [39936, 40448)  kpos[128]
//   [40448, 40960)  red[2][64]
// ============================================================
#define KSTR 40
#define PSTR 74
#define VSTR 74
#define SM_VT   20480
#define SM_INV  39424
#define SM_KPOS 39936
#define SM_RED  40448
#define SM_TOTAL 40960

extern "C" __global__ void __launch_bounds__(256, 3)
attn_kernel(const float* __restrict__ qk, const float* __restrict__ v)
{
    extern __shared__ char smem[];
    uint32_t* s_k32 = (uint32_t*)smem;                // K tile (words)
    uint32_t* s_p32 = (uint32_t*)smem;                // P tile overlays K
    uint32_t* s_v32 = (uint32_t*)(smem + SM_VT);
    __half*   s_v16 = (__half*)(smem + SM_VT);
    float*    s_inv = (float*)(smem + SM_INV);
    int*      s_kpos = (int*)(smem + SM_KPOS);
    float*    s_red = (float*)(smem + SM_RED);

    int tid = threadIdx.x;
    int w = tid >> 5, l = tid & 31;
    int c = blockIdx.x, b = blockIdx.y;
    int h = c >> 6;
    int pc = (c + NCHUNK - 1) & (NCHUNK - 1);

    if (tid < 128) {
        int sel = tid >> 6;                    // 0 = prev chunk, 1 = cur chunk
        int ch = sel ? c : pc;
        s_kpos[tid] = g_st[(b * NH + (ch >> 6)) * SEQ + (ch & 63) * 64 + (tid & 63)];
    }
    __syncthreads();

    // gather: K rows (fp16, word-interleaved) + norms; V^T (fp16)
    int pl = ilv(l);
    #pragma unroll 2
    for (int it = 0; it < 16; it++) {
        int j = w * 16 + it;
        int p = s_kpos[j];
        const float2* src = (const float2*)(qk + ((size_t)b * SEQ + p) * DIM);
        float2 x = src[l];
        __half2 hx = __floats2half2_rn(x.x, x.y);
        s_k32[j * KSTR + pl] = *(uint32_t*)&hx;
        float ss = x.x * x.x + x.y * x.y;
        #pragma unroll
        for (int o = 16; o >= 1; o >>= 1) ss += __shfl_xor_sync(0xffffffffu, ss, o);
        if (l == 0) s_inv[j] = SCALE * rsqrtf(fmaxf(ss, 1e-24f));
        const float* vs = v + ((size_t)b * SEQ + p) * DIM;
        int vidx = ilv(j >> 1) * 2 + (j & 1);
        s_v16[l * (2 * VSTR) + vidx]        = __float2half_rn(vs[l]);
        s_v16[(l + 32) * (2 * VSTR) + vidx] = __float2half_rn(vs[l + 32]);
    }
    __syncthreads();

    int r = l >> 2, q = l & 3;
    int m0 = (w & 3) * 16, nh = w >> 2, n0 = nh * 64;

    // GEMM1: S[16 x 64 per warp] = Q . K^T  (fp16 mma, k16 x 4 steps)
    float acc[8][4];
    #pragma unroll
    for (int j = 0; j < 8; j++)
        #pragma unroll
        for (int k = 0; k < 4; k++) acc[j][k] = 0.f;

    #pragma unroll
    for (int s = 0; s < 4; s++) {
        uint2 A1 = *(const uint2*)&s_k32[(64 + m0 + r) * KSTR + 8 * s + 2 * q];
        uint2 A2 = *(const uint2*)&s_k32[(64 + m0 + 8 + r) * KSTR + 8 * s + 2 * q];
        #pragma unroll
        for (int j = 0; j < 8; j++) {
            uint2 B = *(const uint2*)&s_k32[(n0 + 8 * j + r) * KSTR + 8 * s + 2 * q];
            mma_f16(acc[j], A1.x, A2.x, A1.y, A2.y, B.x, B.y);
        }
    }

    // softmax epilogue (no max-subtraction; dots ~N(0,1))
    int row1 = m0 + r, row2 = row1 + 8;
    int qp1 = s_kpos[64 + row1], qp2 = s_kpos[64 + row2];
    float sum1 = 0.f, sum2 = 0.f;
    #pragma unroll
    for (int j = 0; j < 8; j++) {
        int col0 = n0 + 8 * j + 2 * q, col1 = col0 + 1;
        float i0 = s_inv[col0], i1 = s_inv[col1];
        int k0 = s_kpos[col0], k1 = s_kpos[col1];
        float e;
        e = (k0 == qp1) ? 0.f : __expf(acc[j][0] * i0); acc[j][0] = e; sum1 += e;
        e = (k1 == qp1) ? 0.f : __expf(acc[j][1] * i1); acc[j][1] = e; sum1 += e;
        e = (k0 == qp2) ? 0.f : __expf(acc[j][2] * i0); acc[j][2] = e; sum2 += e;
        e = (k1 == qp2) ? 0.f : __expf(acc[j][3] * i1); acc[j][3] = e; sum2 += e;
    }
    sum1 += __shfl_xor_sync(0xffffffffu, sum1, 1);
    sum1 += __shfl_xor_sync(0xffffffffu, sum1, 2);
    sum2 += __shfl_xor_sync(0xffffffffu, sum2, 1);
    sum2 += __shfl_xor_sync(0xffffffffu, sum2, 2);
    if (q == 0) { s_red[nh * 64 + row1] = sum1; s_red[nh * 64 + row2] = sum2; }
    __syncthreads();          // all GEMM1 K-tile reads complete

    // store P (fp16, word-interleaved) over the K tile
    #pragma unroll
    for (int j = 0; j < 8; j++) {
        int pw = ilv((n0 >> 1) + 4 * j + q);
        __half2 p1 = __floats2half2_rn(acc[j][0], acc[j][1]);
        __half2 p2 = __floats2half2_rn(acc[j][2], acc[j][3]);
        s_p32[row1 * PSTR + pw] = *(uint32_t*)&p1;
        s_p32[row2 * PSTR + pw] = *(uint32_t*)&p2;
    }
    __syncthreads();

    // GEMM2: O[16 x 32 per warp] = P . V  (k16 x 8 steps)
    float o2[4][4];
    #pragma unroll
    for (int j = 0; j < 4; j++)
        #pragma unroll
        for (int k = 0; k < 4; k++) o2[j][k] = 0.f;

    #pragma unroll
    for (int s = 0; s < 8; s++) {
        uint2 A1 = *(const uint2*)&s_p32[(m0 + r) * PSTR + 8 * s + 2 * q];
        uint2 A2 = *(const uint2*)&s_p32[(m0 + 8 + r) * PSTR + 8 * s + 2 * q];
        #pragma unroll
        for (int j = 0; j < 4; j++) {
            uint2 B = *(const uint2*)&s_v32[(nh * 32 + 8 * j + r) * VSTR + 8 * s + 2 * q];
            mma_f16(o2[j], A1.x, A2.x, A1.y, A2.y, B.x, B.y);
        }
    }

    float t1 = s_red[row1] + s_red[64 + row1];
    float t2 = s_red[row2] + s_red[64 + row2];
    float is1 = 1.f / t1, is2 = 1.f / t2;
    size_t obase = (size_t)(b * NH + h) * SEQ;
    if (nh == 0 && q == 0) {
        g_lse[obase + qp1] = logf(t1);
        g_lse[obase + qp2] = logf(t2);
    }
    __half2* og1 = (__half2*)(g_oh + (obase + qp1) * DIM);
    __half2* og2 = (__half2*)(g_oh + (obase + qp2) * DIM);
    #pragma unroll
    for (int j = 0; j < 4; j++) {
        int d = nh * 32 + 8 * j + 2 * q;
        og1[d >> 1] = __floats2half2_rn(o2[j][0] * is1, o2[j][1] * is1);
        og2[d >> 1] = __floats2half2_rn(o2[j][2] * is2, o2[j][3] * is2);
    }
}

// ============================================================
// Kernel 4: combine hash rounds (reads fp16 per-hash outputs)
// ============================================================
extern "C" __global__ void __launch_bounds__(256)
combine_kernel(float* __restrict__ out)
{
    int wid = blockIdx.x * 8 + (threadIdx.x >> 5);
    int l = threadIdx.x & 31;
    int b = wid >> 12, t = wid & 4095;

    float lse[NH];
    #pragma unroll
    for (int h = 0; h < NH; h++) lse[h] = g_lse[(b * NH + h) * SEQ + t];
    float m = lse[0];
    #pragma unroll
    for (int h = 1; h < NH; h++) m = fmaxf(m, lse[h]);
    float Z = 0.f;
    #pragma unroll
    for (int h = 0; h < NH; h++) Z += __expf(lse[h] - m);
    float iz = 1.f / Z;

    float2 a = make_float2(0.f, 0.f);
    #pragma unroll
    for (int h = 0; h < NH; h++) {
        float wgt = __expf(lse[h] - m) * iz;
        const __half2* row = (const __half2*)(g_oh + ((size_t)((b * NH + h) * SEQ) + t) * DIM);
        float2 x = __half22float2(row[l]);
        a.x += wgt * x.x;
        a.y += wgt * x.y;
    }
    ((float2*)out)[((size_t)b * SEQ + t) * 32 + l] = a;
}

// ============================================================
extern "C" void kernel_launch(void* const* d_in, const int* in_sizes, int n_in,
                              void* d_out, int out_size)
{
    const float* qk  = (const float*)d_in[0];
    const float* v   = (const float*)d_in[1];
    const float* rot = (const float*)d_in[2];

    cudaFuncSetAttribute(hash_kernel, cudaFuncAttributeMaxDynamicSharedMemorySize, 65536);
    cudaFuncSetAttribute(attn_kernel, cudaFuncAttributeMaxDynamicSharedMemorySize, SM_TOTAL);

    hash_kernel<<<(BATCH * SEQ) / 128, 128, 65536>>>(qk, rot);
    sort_kernel<<<BATCH * NH, 128>>>();
    attn_kernel<<<dim3(NCHUNK, BATCH), 256, SM_TOTAL>>>(qk, v);
    combine_kernel<<<(BATCH * SEQ) / 8, 256>>>((float*)d_out);
}

// round 6
// speedup vs baseline: 2.5769x; 1.4041x over previous
#include <cuda_runtime.h>
#include <cuda_fp16.h>
#include <math.h>
#include <stdint.h>

#define BATCH 16
#define SEQ   4096
#define DIM   64
#define NH    8
#define NB    64
#define NCHUNK 512
#define SCALE 0.125f

// ---- fp16 mma.sync m16n8k16 + ldmatrix (baseline PTX) ----
__device__ __forceinline__ void mma_f16(float* c, uint32_t a0, uint32_t a1, uint32_t a2, uint32_t a3,
                                        uint32_t b0, uint32_t b1) {
    asm volatile("mma.sync.aligned.m16n8k16.row.col.f32.f16.f16.f32 "
                 "{%0,%1,%2,%3}, {%4,%5,%6,%7}, {%8,%9}, {%0,%1,%2,%3};"
                 : "+f"(c[0]), "+f"(c[1]), "+f"(c[2]), "+f"(c[3])
                 : "r"(a0), "r"(a1), "r"(a2), "r"(a3), "r"(b0), "r"(b1));
}
__device__ __forceinline__ void ldsm_x4(uint32_t addr, uint32_t& r0, uint32_t& r1, uint32_t& r2, uint32_t& r3) {
    asm volatile("ldmatrix.sync.aligned.m8n8.x4.shared.b16 {%0,%1,%2,%3}, [%4];"
                 : "=r"(r0), "=r"(r1), "=r"(r2), "=r"(r3) : "r"(addr));
}
__device__ __forceinline__ void ldsm_x4_t(uint32_t addr, uint32_t& r0, uint32_t& r1, uint32_t& r2, uint32_t& r3) {
    asm volatile("ldmatrix.sync.aligned.m8n8.x4.trans.shared.b16 {%0,%1,%2,%3}, [%4];"
                 : "=r"(r0), "=r"(r1), "=r"(r2), "=r"(r3) : "r"(addr));
}
__device__ __forceinline__ uint32_t smem_u32(const void* p) {
    uint32_t a;
    asm("{ .reg .u64 t; cvta.to.shared.u64 t, %1; cvt.u32.u64 %0, t; }" : "=r"(a) : "l"(p));
    return a;
}

// ---- packed f32x2 for hash kernel ----
__device__ __forceinline__ unsigned long long pk2(float x, float y) {
    unsigned long long r; asm("mov.b64 %0, {%1,%2};" : "=l"(r) : "f"(x), "f"(y)); return r;
}
__device__ __forceinline__ float2 upk2(unsigned long long a) {
    float2 r; asm("mov.b64 {%0,%1}, %2;" : "=f"(r.x), "=f"(r.y) : "l"(a)); return r;
}
#define FFMA2(d, a, b) asm("fma.rn.f32x2 %0, %1, %2, %0;" : "+l"(d) : "l"(a), "l"(b))

// ---- scratch ----
__device__ unsigned char g_buckets[BATCH * NH * SEQ];
__device__ int           g_st[BATCH * NH * SEQ];
__device__ __half        g_q16[(size_t)BATCH * SEQ * DIM];       // 8 MB raw fp16 qk
__device__ __half        g_v16[(size_t)BATCH * SEQ * DIM];       // 8 MB raw fp16 v
__device__ float         g_inv[BATCH * SEQ];                     // SCALE / max(||k||, 1e-12)
__device__ __half        g_oh[(size_t)BATCH * NH * SEQ * DIM];   // 64 MB per-hash outputs
__device__ float         g_lse[BATCH * NH * SEQ];

// ============================================================
// Kernel 0: fp32 -> fp16 prep (coalesced)
// ============================================================
extern "C" __global__ void __launch_bounds__(256)
prep_kernel(const float* __restrict__ qk, const float* __restrict__ v)
{
    size_t i = (size_t)blockIdx.x * 256 + threadIdx.x;     // x4 floats
    float4 a = ((const float4*)qk)[i];
    __half2 h0 = __floats2half2_rn(a.x, a.y), h1 = __floats2half2_rn(a.z, a.w);
    ((uint2*)g_q16)[i] = make_uint2(*(uint32_t*)&h0, *(uint32_t*)&h1);
    float4 bb = ((const float4*)v)[i];
    h0 = __floats2half2_rn(bb.x, bb.y); h1 = __floats2half2_rn(bb.z, bb.w);
    ((uint2*)g_v16)[i] = make_uint2(*(uint32_t*)&h0, *(uint32_t*)&h1);
}

// ============================================================
// Kernel 1: LSH hashing (FFMA2) + per-token inverse norm
// ============================================================
extern "C" __global__ void __launch_bounds__(128)
hash_kernel(const float* __restrict__ qk, const float* __restrict__ rot)
{
    extern __shared__ float rot_s[];
    int tid = threadIdx.x;
    #pragma unroll
    for (int k = 0; k < 128; k++) rot_s[tid + k * 128] = rot[tid + k * 128];
    __syncthreads();

    int g = blockIdx.x * 128 + tid;
    int b = g >> 12, t = g & 4095;

    float q[64];
    float ss = 0.f;
    const float4* qp = (const float4*)(qk + (size_t)g * 64);
    #pragma unroll
    for (int i = 0; i < 16; i++) {
        float4 x = qp[i];
        q[4*i] = x.x; q[4*i+1] = x.y; q[4*i+2] = x.z; q[4*i+3] = x.w;
        ss += x.x * x.x + x.y * x.y + x.z * x.z + x.w * x.w;
    }
    g_inv[g] = SCALE / fmaxf(sqrtf(ss), 1e-12f);

    for (int h = 0; h < NH; h++) {
        unsigned long long acc2[16];
        #pragma unroll
        for (int c = 0; c < 16; c++) acc2[c] = 0ull;
        #pragma unroll 4
        for (int f = 0; f < 64; f++) {
            unsigned long long q2 = pk2(q[f], q[f]);
            const ulonglong2* rp = (const ulonglong2*)(rot_s + f * 256 + h * 32);
            #pragma unroll
            for (int c4 = 0; c4 < 8; c4++) {
                ulonglong2 r2 = rp[c4];
                FFMA2(acc2[c4*2],   q2, r2.x);
                FFMA2(acc2[c4*2+1], q2, r2.y);
            }
        }
        float best = -1e30f; int bi = 0;
        #pragma unroll
        for (int c = 0; c < 16; c++) {
            float2 d = upk2(acc2[c]);
            if (d.x > best) { best = d.x; bi = 2*c; }
            if (d.y > best) { best = d.y; bi = 2*c+1; }
        }
        #pragma unroll
        for (int c = 0; c < 16; c++) {
            float2 d = upk2(acc2[c]);
            if (-d.x > best) { best = -d.x; bi = 32 + 2*c; }
            if (-d.y > best) { best = -d.y; bi = 32 + 2*c+1; }
        }
        g_buckets[(b * NH + h) * SEQ + t] = (unsigned char)bi;
    }
}

// ============================================================
// Kernel 2: stable counting sort per (batch, hash)
// ============================================================
extern "C" __global__ void __launch_bounds__(128)
sort_kernel()
{
    __shared__ int cnt[NB * 128];
    __shared__ int totals[NB];
    int tid = threadIdx.x;
    const unsigned char* bk = g_buckets + (size_t)blockIdx.x * SEQ;

    #pragma unroll
    for (int k = 0; k < NB; k++) cnt[k * 128 + tid] = 0;
    __syncthreads();

    int base = tid * 32;
    #pragma unroll
    for (int p = 0; p < 32; p++) { int c = bk[base + p]; cnt[c * 128 + tid]++; }
    __syncthreads();

    if (tid < NB) {
        int s = 0;
        for (int u = 0; u < 128; u++) s += cnt[tid * 128 + u];
        totals[tid] = s;
    }
    __syncthreads();
    if (tid == 0) {
        int r = 0;
        for (int c = 0; c < NB; c++) { int x = totals[c]; totals[c] = r; r += x; }
    }
    __syncthreads();
    if (tid < NB) {
        int run = totals[tid];
        for (int u = 0; u < 128; u++) { int x = cnt[tid * 128 + u]; cnt[tid * 128 + u] = run; run += x; }
    }
    __syncthreads();

    int* st = g_st + (size_t)blockIdx.x * SEQ;
    #pragma unroll
    for (int p = 0; p < 32; p++) {
        int pos = base + p;
        int c = bk[pos];
        int s = cnt[c * 128 + tid]++;
        st[s] = pos;
    }
}

// ============================================================
// Kernel 3: fp16 mma attention with ldmatrix. Block = (chunk, batch).
// SMEM (bytes):
//   [0, 16384)      KQ tile: 128 rows x 128B (rows 0-63 prev chunk, 64-127 cur)
//                   swizzle: chunk ^ (row & 7).  P tile (64 rows x 256B) overlays.
//   [16384, 32768)  V tile: 128 rows x 128B (row-major, same swizzle)
//   [32768, 33280)  inv[128]
//   [33280, 33792)  kpos[128]
//   [33792, 34304)  red[2][64]
// ============================================================
#define SM_V    16384
#define SM_INV  32768
#define SM_KPOS 33280
#define SM_RED  33792
#define SM_TOTAL 34304

extern "C" __global__ void __launch_bounds__(256, 3)
attn_kernel()
{
    extern __shared__ char smem[];
    uint32_t sb = smem_u32(smem);
    float* s_inv = (float*)(smem + SM_INV);
    int*   s_kpos = (int*)(smem + SM_KPOS);
    float* s_red = (float*)(smem + SM_RED);

    int tid = threadIdx.x;
    int w = tid >> 5, l = tid & 31;
    int c = blockIdx.x, b = blockIdx.y;
    int h = c >> 6;
    int pc = (c + NCHUNK - 1) & (NCHUNK - 1);

    if (tid < 128) {
        int sel = tid >> 6;                    // 0 = prev chunk, 1 = cur chunk
        int ch = sel ? c : pc;
        int p = g_st[(b * NH + (ch >> 6)) * SEQ + (ch & 63) * 64 + (tid & 63)];
        s_kpos[tid] = p;
        s_inv[tid] = g_inv[b * SEQ + p];
    }
    __syncthreads();

    // gather: 256 rows x 128B, one uint4 per (thread, iter)
    {
        int lane8 = tid & 7, rbase = tid >> 3;
        const __half* qsrc = g_q16 + (size_t)b * SEQ * DIM;
        const __half* vsrc = g_v16 + (size_t)b * SEQ * DIM;
        #pragma unroll
        for (int it = 0; it < 8; it++) {
            int row = rbase + 32 * it;         // 0..255
            int j = row & 127;
            int p = s_kpos[j];
            const __half* srcb = (row < 128) ? qsrc : vsrc;
            uint4 val = *((const uint4*)(srcb + (size_t)p * DIM) + lane8);
            char* dst = smem + ((row < 128) ? 0 : SM_V) + j * 128 + ((lane8 ^ (j & 7)) << 4);
            *(uint4*)dst = val;
        }
    }
    __syncthreads();

    int r = l >> 2, q = l & 3;
    int m0 = (w & 3) * 16, nh = w >> 2, n0 = nh * 64;

    // GEMM1: S[16 x 64 per warp] = Q . K^T   (ldmatrix-fed)
    float acc[8][4];
    #pragma unroll
    for (int j = 0; j < 8; j++)
        #pragma unroll
        for (int k = 0; k < 4; k++) acc[j][k] = 0.f;

    int arow = 64 + m0 + (l & 15);
    #pragma unroll
    for (int s = 0; s < 4; s++) {
        int ca = 2 * s + (l >> 4);
        uint32_t a0, a1, a2, a3;
        ldsm_x4(sb + arow * 128 + ((ca ^ (arow & 7)) << 4), a0, a1, a2, a3);
        #pragma unroll
        for (int jp = 0; jp < 4; jp++) {
            int krow = n0 + 16 * jp + (l & 15);
            uint32_t b0, b1, b2, b3;
            ldsm_x4(sb + krow * 128 + ((ca ^ (krow & 7)) << 4), b0, b1, b2, b3);
            mma_f16(acc[2*jp],   a0, a1, a2, a3, b0, b2);
            mma_f16(acc[2*jp+1], a0, a1, a2, a3, b1, b3);
        }
    }

    // softmax epilogue (no max-subtraction; dots ~N(0,1))
    int row1 = m0 + r, row2 = row1 + 8;
    int qp1 = s_kpos[64 + row1], qp2 = s_kpos[64 + row2];
    float sum1 = 0.f, sum2 = 0.f;
    #pragma unroll
    for (int j = 0; j < 8; j++) {
        int col0 = n0 + 8 * j + 2 * q, col1 = col0 + 1;
        float i0 = s_inv[col0], i1 = s_inv[col1];
        int k0 = s_kpos[col0], k1 = s_kpos[col1];
        float e;
        e = (k0 == qp1) ? 0.f : __expf(acc[j][0] * i0); acc[j][0] = e; sum1 += e;
        e = (k1 == qp1) ? 0.f : __expf(acc[j][1] * i1); acc[j][1] = e; sum1 += e;
        e = (k0 == qp2) ? 0.f : __expf(acc[j][2] * i0); acc[j][2] = e; sum2 += e;
        e = (k1 == qp2) ? 0.f : __expf(acc[j][3] * i1); acc[j][3] = e; sum2 += e;
    }
    sum1 += __shfl_xor_sync(0xffffffffu, sum1, 1);
    sum1 += __shfl_xor_sync(0xffffffffu, sum1, 2);
    sum2 += __shfl_xor_sync(0xffffffffu, sum2, 1);
    sum2 += __shfl_xor_sync(0xffffffffu, sum2, 2);
    if (q == 0) { s_red[nh * 64 + row1] = sum1; s_red[nh * 64 + row2] = sum2; }
    __syncthreads();          // all GEMM1 KQ-tile reads complete

    // store P (fp16) over the KQ tile: P row = 256B, swizzled
    #pragma unroll
    for (int j = 0; j < 8; j++) {
        int cc = (n0 >> 3) + j;
        __half2 p1 = __floats2half2_rn(acc[j][0], acc[j][1]);
        __half2 p2 = __floats2half2_rn(acc[j][2], acc[j][3]);
        *(__half2*)(smem + row1 * 256 + ((cc ^ (row1 & 7)) << 4) + 4 * q) = p1;
        *(__half2*)(smem + row2 * 256 + ((cc ^ (row2 & 7)) << 4) + 4 * q) = p2;
    }
    __syncthreads();

    // GEMM2: O[16 x 32 per warp] = P . V   (V via ldmatrix.trans)
    float o2[4][4];
    #pragma unroll
    for (int j = 0; j < 4; j++)
        #pragma unroll
        for (int k = 0; k < 4; k++) o2[j][k] = 0.f;

    int prow = m0 + (l & 15);
    #pragma unroll
    for (int s = 0; s < 8; s++) {
        int ca = 2 * s + (l >> 4);                 // 0..15 chunks per P row
        uint32_t a0, a1, a2, a3;
        ldsm_x4(sb + prow * 256 + ((ca ^ (prow & 7)) << 4), a0, a1, a2, a3);
        int vrow = 16 * s + (l & 15);
        #pragma unroll
        for (int dp = 0; dp < 2; dp++) {
            int cv = nh * 4 + 2 * dp + (l >> 4);
            uint32_t r0, r1, r2, r3;
            ldsm_x4_t(sb + SM_V + vrow * 128 + ((cv ^ (vrow & 7)) << 4), r0, r1, r2, r3);
            mma_f16(o2[2*dp],   a0, a1, a2, a3, r0, r1);
            mma_f16(o2[2*dp+1], a0, a1, a2, a3, r2, r3);
        }
    }

    float t1 = s_red[row1] + s_red[64 + row1];
    float t2 = s_red[row2] + s_red[64 + row2];
    float is1 = 1.f / t1, is2 = 1.f / t2;
    size_t obase = (size_t)(b * NH + h) * SEQ;
    if (nh == 0 && q == 0) {
        g_lse[obase + qp1] = logf(t1);
        g_lse[obase + qp2] = logf(t2);
    }
    __half2* og1 = (__half2*)(g_oh + (obase + qp1) * DIM);
    __half2* og2 = (__half2*)(g_oh + (obase + qp2) * DIM);
    #pragma unroll
    for (int j = 0; j < 4; j++) {
        int d = nh * 32 + 8 * j + 2 * q;
        og1[d >> 1] = __floats2half2_rn(o2[j][0] * is1, o2[j][1] * is1);
        og2[d >> 1] = __floats2half2_rn(o2[j][2] * is2, o2[j][3] * is2);
    }
}

// ============================================================
// Kernel 4: combine hash rounds (fp16 per-hash outputs)
// ============================================================
extern "C" __global__ void __launch_bounds__(256)
combine_kernel(float* __restrict__ out)
{
    int wid = blockIdx.x * 8 + (threadIdx.x >> 5);
    int l = threadIdx.x & 31;
    int b = wid >> 12, t = wid & 4095;

    float lse[NH];
    #pragma unroll
    for (int h = 0; h < NH; h++) lse[h] = g_lse[(b * NH + h) * SEQ + t];
    float m = lse[0];
    #pragma unroll
    for (int h = 1; h < NH; h++) m = fmaxf(m, lse[h]);
    float Z = 0.f;
    #pragma unroll
    for (int h = 0; h < NH; h++) Z += __expf(lse[h] - m);
    float iz = 1.f / Z;

    float2 a = make_float2(0.f, 0.f);
    #pragma unroll
    for (int h = 0; h < NH; h++) {
        float wgt = __expf(lse[h] - m) * iz;
        const __half2* row = (const __half2*)(g_oh + ((size_t)((b * NH + h) * SEQ) + t) * DIM);
        float2 x = __half22float2(row[l]);
        a.x += wgt * x.x;
        a.y += wgt * x.y;
    }
    ((float2*)out)[((size_t)b * SEQ + t) * 32 + l] = a;
}

// ============================================================
extern "C" void kernel_launch(void* const* d_in, const int* in_sizes, int n_in,
                              void* d_out, int out_size)
{
    const float* qk  = (const float*)d_in[0];
    const float* v   = (const float*)d_in[1];
    const float* rot = (const float*)d_in[2];

    cudaFuncSetAttribute(hash_kernel, cudaFuncAttributeMaxDynamicSharedMemorySize, 65536);
    cudaFuncSetAttribute(attn_kernel, cudaFuncAttributeMaxDynamicSharedMemorySize, SM_TOTAL);

    prep_kernel<<<(BATCH * SEQ * DIM) / 4 / 256, 256>>>(qk, v);
    hash_kernel<<<(BATCH * SEQ) / 128, 128, 65536>>>(qk, rot);
    sort_kernel<<<BATCH * NH, 128>>>();
    attn_kernel<<<dim3(NCHUNK, BATCH), 256, SM_TOTAL>>>();
    combine_kernel<<<(BATCH * SEQ) / 8, 256>>>((float*)d_out);
}

// round 7
// speedup vs baseline: 2.7478x; 1.0663x over previous
#include <cuda_runtime.h>
#include <cuda_fp16.h>
#include <math.h>
#include <stdint.h>

#define BATCH 16
#define SEQ   4096
#define DIM   64
#define NH    8
#define NB    64
#define NCHUNK 512
#define SCALE 0.125f

// ---- fp16 mma.sync m16n8k16 + ldmatrix (baseline PTX) ----
__device__ __forceinline__ void mma_f16(float* c, uint32_t a0, uint32_t a1, uint32_t a2, uint32_t a3,
                                        uint32_t b0, uint32_t b1) {
    asm volatile("mma.sync.aligned.m16n8k16.row.col.f32.f16.f16.f32 "
                 "{%0,%1,%2,%3}, {%4,%5,%6,%7}, {%8,%9}, {%0,%1,%2,%3};"
                 : "+f"(c[0]), "+f"(c[1]), "+f"(c[2]), "+f"(c[3])
                 : "r"(a0), "r"(a1), "r"(a2), "r"(a3), "r"(b0), "r"(b1));
}
__device__ __forceinline__ void ldsm_x4(uint32_t addr, uint32_t& r0, uint32_t& r1, uint32_t& r2, uint32_t& r3) {
    asm volatile("ldmatrix.sync.aligned.m8n8.x4.shared.b16 {%0,%1,%2,%3}, [%4];"
                 : "=r"(r0), "=r"(r1), "=r"(r2), "=r"(r3) : "r"(addr));
}
__device__ __forceinline__ void ldsm_x4_t(uint32_t addr, uint32_t& r0, uint32_t& r1, uint32_t& r2, uint32_t& r3) {
    asm volatile("ldmatrix.sync.aligned.m8n8.x4.trans.shared.b16 {%0,%1,%2,%3}, [%4];"
                 : "=r"(r0), "=r"(r1), "=r"(r2), "=r"(r3) : "r"(addr));
}
__device__ __forceinline__ uint32_t smem_u32(const void* p) {
    uint32_t a;
    asm("{ .reg .u64 t; cvta.to.shared.u64 t, %1; cvt.u32.u64 %0, t; }" : "=r"(a) : "l"(p));
    return a;
}

// ---- packed f32x2 for hash kernel ----
__device__ __forceinline__ unsigned long long pk2(float x, float y) {
    unsigned long long r; asm("mov.b64 %0, {%1,%2};" : "=l"(r) : "f"(x), "f"(y)); return r;
}
__device__ __forceinline__ float2 upk2(unsigned long long a) {
    float2 r; asm("mov.b64 {%0,%1}, %2;" : "=f"(r.x), "=f"(r.y) : "l"(a)); return r;
}
#define FFMA2(d, a, b) asm("fma.rn.f32x2 %0, %1, %2, %0;" : "+l"(d) : "l"(a), "l"(b))

// ---- scratch ----
__device__ unsigned char g_buckets[BATCH * NH * SEQ];
__device__ int           g_st[BATCH * NH * SEQ];
__device__ __half        g_q16[(size_t)BATCH * SEQ * DIM];       // 8 MB raw fp16 qk
__device__ __half        g_v16[(size_t)BATCH * SEQ * DIM];       // 8 MB raw fp16 v
__device__ float         g_inv[BATCH * SEQ];                     // SCALE / max(||k||, 1e-12)
__device__ __half        g_oh[(size_t)BATCH * NH * SEQ * DIM];   // 64 MB per-hash outputs
__device__ float         g_lse[BATCH * NH * SEQ];

// ============================================================
// Kernel 0: prep — fp16 copies of qk/v + per-token inverse norm.
// One warp per token row.
// ============================================================
extern "C" __global__ void __launch_bounds__(256)
prep_kernel(const float* __restrict__ qk, const float* __restrict__ v)
{
    int row = blockIdx.x * 8 + (threadIdx.x >> 5);
    int l = threadIdx.x & 31;
    float2 xq = ((const float2*)(qk + (size_t)row * DIM))[l];
    float ss = xq.x * xq.x + xq.y * xq.y;
    #pragma unroll
    for (int o = 16; o >= 1; o >>= 1) ss += __shfl_xor_sync(0xffffffffu, ss, o);
    if (l == 0) g_inv[row] = SCALE / fmaxf(sqrtf(ss), 1e-12f);
    ((__half2*)(g_q16 + (size_t)row * DIM))[l] = __floats2half2_rn(xq.x, xq.y);
    float2 xv = ((const float2*)(v + (size_t)row * DIM))[l];
    ((__half2*)(g_v16 + (size_t)row * DIM))[l] = __floats2half2_rn(xv.x, xv.y);
}

// ============================================================
// Kernel 1: LSH hashing (FFMA2)
// ============================================================
extern "C" __global__ void __launch_bounds__(128)
hash_kernel(const float* __restrict__ qk, const float* __restrict__ rot)
{
    extern __shared__ float rot_s[];
    int tid = threadIdx.x;
    #pragma unroll
    for (int k = 0; k < 128; k++) rot_s[tid + k * 128] = rot[tid + k * 128];
    __syncthreads();

    int g = blockIdx.x * 128 + tid;
    int b = g >> 12, t = g & 4095;

    float q[64];
    const float4* qp = (const float4*)(qk + (size_t)g * 64);
    #pragma unroll
    for (int i = 0; i < 16; i++) {
        float4 x = qp[i];
        q[4*i] = x.x; q[4*i+1] = x.y; q[4*i+2] = x.z; q[4*i+3] = x.w;
    }

    for (int h = 0; h < NH; h++) {
        unsigned long long acc2[16];
        #pragma unroll
        for (int c = 0; c < 16; c++) acc2[c] = 0ull;
        #pragma unroll 4
        for (int f = 0; f < 64; f++) {
            unsigned long long q2 = pk2(q[f], q[f]);
            const ulonglong2* rp = (const ulonglong2*)(rot_s + f * 256 + h * 32);
            #pragma unroll
            for (int c4 = 0; c4 < 8; c4++) {
                ulonglong2 r2 = rp[c4];
                FFMA2(acc2[c4*2],   q2, r2.x);
                FFMA2(acc2[c4*2+1], q2, r2.y);
            }
        }
        float best = -1e30f; int bi = 0;
        #pragma unroll
        for (int c = 0; c < 16; c++) {
            float2 d = upk2(acc2[c]);
            if (d.x > best) { best = d.x; bi = 2*c; }
            if (d.y > best) { best = d.y; bi = 2*c+1; }
        }
        #pragma unroll
        for (int c = 0; c < 16; c++) {
            float2 d = upk2(acc2[c]);
            if (-d.x > best) { best = -d.x; bi = 32 + 2*c; }
            if (-d.y > best) { best = -d.y; bi = 32 + 2*c+1; }
        }
        g_buckets[(b * NH + h) * SEQ + t] = (unsigned char)bi;
    }
}

// ============================================================
// Kernel 2: stable counting sort per (batch, hash)
// ============================================================
extern "C" __global__ void __launch_bounds__(128)
sort_kernel()
{
    __shared__ int cnt[NB * 128];
    __shared__ int totals[NB];
    int tid = threadIdx.x;
    const unsigned char* bk = g_buckets + (size_t)blockIdx.x * SEQ;

    #pragma unroll
    for (int k = 0; k < NB; k++) cnt[k * 128 + tid] = 0;
    __syncthreads();

    int base = tid * 32;
    #pragma unroll
    for (int p = 0; p < 32; p++) { int c = bk[base + p]; cnt[c * 128 + tid]++; }
    __syncthreads();

    if (tid < NB) {
        int s = 0;
        for (int u = 0; u < 128; u++) s += cnt[tid * 128 + u];
        totals[tid] = s;
    }
    __syncthreads();
    if (tid == 0) {
        int r = 0;
        for (int c = 0; c < NB; c++) { int x = totals[c]; totals[c] = r; r += x; }
    }
    __syncthreads();
    if (tid < NB) {
        int run = totals[tid];
        for (int u = 0; u < 128; u++) { int x = cnt[tid * 128 + u]; cnt[tid * 128 + u] = run; run += x; }
    }
    __syncthreads();

    int* st = g_st + (size_t)blockIdx.x * SEQ;
    #pragma unroll
    for (int p = 0; p < 32; p++) {
        int pos = base + p;
        int c = bk[pos];
        int s = cnt[c * 128 + tid]++;
        st[s] = pos;
    }
}

// ============================================================
// Kernel 3: fp16 mma attention, chunk PAIR per block, P in registers.
// Tile rows: 0-63 = prev(c0), 64-127 = c0, 128-191 = c1.
// Warp w (0-7): Q rows 64 + 16w .. ; key window base = (w<4) ? 0 : 64.
// SMEM (bytes):
//   [0, 24576)      KQ tile: 192 rows x 128B, swizzle chunk^(row&7)
//   [24576, 49152)  V tile: 192 rows x 128B, same swizzle
//   [49152, 49920)  kpos[192]
//   [49920, 50688)  inv[192]
// ============================================================
#define SM_V    24576
#define SM_KPOS 49152
#define SM_INV  49920
#define SM_TOTAL 50688

extern "C" __global__ void __launch_bounds__(256, 2)
attn_kernel()
{
    extern __shared__ char smem[];
    uint32_t sb = smem_u32(smem);
    int*   s_kpos = (int*)(smem + SM_KPOS);
    float* s_inv  = (float*)(smem + SM_INV);

    int tid = threadIdx.x;
    int w = tid >> 5, l = tid & 31;
    int pair = blockIdx.x, b = blockIdx.y;
    int c0 = 2 * pair;
    int pc = (c0 + NCHUNK - 1) & (NCHUNK - 1);
    int h = c0 >> 6;

    if (tid < 192) {
        int sel = tid >> 6;                          // 0=prev, 1=c0, 2=c1
        int ch = (sel == 0) ? pc : (c0 + sel - 1);
        int p = g_st[(b * NH + (ch >> 6)) * SEQ + (ch & 63) * 64 + (tid & 63)];
        s_kpos[tid] = p;
        s_inv[tid] = g_inv[b * SEQ + p];
    }
    __syncthreads();

    // gather 192 KQ rows + 192 V rows (uint4 per thread-iter)
    {
        int lane8 = tid & 7, rbase = tid >> 3;
        const __half* qsrc = g_q16 + (size_t)b * SEQ * DIM;
        const __half* vsrc = g_v16 + (size_t)b * SEQ * DIM;
        #pragma unroll
        for (int it = 0; it < 6; it++) {
            int j = rbase + 32 * it;                 // 0..191
            int p = s_kpos[j];
            uint32_t doff = j * 128 + ((lane8 ^ (j & 7)) << 4);
            *(uint4*)(smem + doff)        = *((const uint4*)(qsrc + (size_t)p * DIM) + lane8);
            *(uint4*)(smem + SM_V + doff) = *((const uint4*)(vsrc + (size_t)p * DIM) + lane8);
        }
    }
    __syncthreads();

    int r = l >> 2, q = l & 3;
    int base = (w < 4) ? 0 : 64;                     // key window start
    int qrow = 64 + 16 * w;                          // tile row of warp's first Q row

    // GEMM1: S[16 x 128] per warp = Q . K^T
    float acc[16][4];
    #pragma unroll
    for (int j = 0; j < 16; j++)
        #pragma unroll
        for (int k = 0; k < 4; k++) acc[j][k] = 0.f;

    int arow = qrow + (l & 15);
    #pragma unroll
    for (int s = 0; s < 4; s++) {
        int ca = 2 * s + (l >> 4);
        uint32_t a0, a1, a2, a3;
        ldsm_x4(sb + arow * 128 + ((ca ^ (arow & 7)) << 4), a0, a1, a2, a3);
        #pragma unroll
        for (int jp = 0; jp < 8; jp++) {
            int krow = base + 16 * jp + (l & 15);
            uint32_t b0, b1, b2, b3;
            ldsm_x4(sb + krow * 128 + ((ca ^ (krow & 7)) << 4), b0, b1, b2, b3);
            mma_f16(acc[2*jp],   a0, a1, a2, a3, b0, b2);
            mma_f16(acc[2*jp+1], a0, a1, a2, a3, b1, b3);
        }
    }

    // epilogue: scale by per-key inv, self-mask, exp (no max-subtraction)
    int row1 = qrow + r, row2 = row1 + 8;
    int qp1 = s_kpos[row1], qp2 = s_kpos[row2];
    float sum1 = 0.f, sum2 = 0.f;
    #pragma unroll
    for (int j = 0; j < 16; j++) {
        int col = base + 8 * j + 2 * q;
        float2 iv = *(const float2*)&s_inv[col];
        int2  kp = *(const int2*)&s_kpos[col];
        float e;
        e = (kp.x == qp1) ? 0.f : __expf(acc[j][0] * iv.x); acc[j][0] = e; sum1 += e;
        e = (kp.y == qp1) ? 0.f : __expf(acc[j][1] * iv.y); acc[j][1] = e; sum1 += e;
        e = (kp.x == qp2) ? 0.f : __expf(acc[j][2] * iv.x); acc[j][2] = e; sum2 += e;
        e = (kp.y == qp2) ? 0.f : __expf(acc[j][3] * iv.y); acc[j][3] = e; sum2 += e;
    }
    sum1 += __shfl_xor_sync(0xffffffffu, sum1, 1);
    sum1 += __shfl_xor_sync(0xffffffffu, sum1, 2);
    sum2 += __shfl_xor_sync(0xffffffffu, sum2, 1);
    sum2 += __shfl_xor_sync(0xffffffffu, sum2, 2);

    // pack P to fp16 A-fragments in registers (no SMEM round-trip)
    uint32_t pa[32];
    #pragma unroll
    for (int s = 0; s < 8; s++) {
        __half2 t0 = __floats2half2_rn(acc[2*s][0],   acc[2*s][1]);
        __half2 t1 = __floats2half2_rn(acc[2*s][2],   acc[2*s][3]);
        __half2 t2 = __floats2half2_rn(acc[2*s+1][0], acc[2*s+1][1]);
        __half2 t3 = __floats2half2_rn(acc[2*s+1][2], acc[2*s+1][3]);
        pa[4*s]   = *(uint32_t*)&t0;
        pa[4*s+1] = *(uint32_t*)&t1;
        pa[4*s+2] = *(uint32_t*)&t2;
        pa[4*s+3] = *(uint32_t*)&t3;
    }

    // GEMM2: O[16 x 64] per warp = P . V  (V via ldmatrix.trans)
    float o2[8][4];
    #pragma unroll
    for (int j = 0; j < 8; j++)
        #pragma unroll
        for (int k = 0; k < 4; k++) o2[j][k] = 0.f;

    #pragma unroll
    for (int s = 0; s < 8; s++) {
        int vrow = base + 16 * s + (l & 15);
        #pragma unroll
        for (int dp = 0; dp < 4; dp++) {
            int cv = 2 * dp + (l >> 4);
            uint32_t r0, r1, r2, r3;
            ldsm_x4_t(sb + SM_V + vrow * 128 + ((cv ^ (vrow & 7)) << 4), r0, r1, r2, r3);
            mma_f16(o2[2*dp],   pa[4*s], pa[4*s+1], pa[4*s+2], pa[4*s+3], r0, r1);
            mma_f16(o2[2*dp+1], pa[4*s], pa[4*s+1], pa[4*s+2], pa[4*s+3], r2, r3);
        }
    }

    float is1 = 1.f / sum1, is2 = 1.f / sum2;
    size_t obase = (size_t)(b * NH + h) * SEQ;
    if (q == 0) {
        g_lse[obase + qp1] = logf(sum1);
        g_lse[obase + qp2] = logf(sum2);
    }
    __half2* og1 = (__half2*)(g_oh + (obase + qp1) * DIM);
    __half2* og2 = (__half2*)(g_oh + (obase + qp2) * DIM);
    #pragma unroll
    for (int j = 0; j < 8; j++) {
        int d = (8 * j + 2 * q) >> 1;
        og1[d] = __floats2half2_rn(o2[j][0] * is1, o2[j][1] * is1);
        og2[d] = __floats2half2_rn(o2[j][2] * is2, o2[j][3] * is2);
    }
}

// ============================================================
// Kernel 4: combine hash rounds (fp16 per-hash outputs)
// ============================================================
extern "C" __global__ void __launch_bounds__(256)
combine_kernel(float* __restrict__ out)
{
    int wid = blockIdx.x * 8 + (threadIdx.x >> 5);
    int l = threadIdx.x & 31;
    int b = wid >> 12, t = wid & 4095;

    float lse[NH];
    #pragma unroll
    for (int h = 0; h < NH; h++) lse[h] = g_lse[(b * NH + h) * SEQ + t];
    float m = lse[0];
    #pragma unroll
    for (int h = 1; h < NH; h++) m = fmaxf(m, lse[h]);
    float Z = 0.f;
    #pragma unroll
    for (int h = 0; h < NH; h++) Z += __expf(lse[h] - m);
    float iz = 1.f / Z;

    float2 a = make_float2(0.f, 0.f);
    #pragma unroll
    for (int h = 0; h < NH; h++) {
        float wgt = __expf(lse[h] - m) * iz;
        const __half2* row = (const __half2*)(g_oh + ((size_t)((b * NH + h) * SEQ) + t) * DIM);
        float2 x = __half22float2(row[l]);
        a.x += wgt * x.x;
        a.y += wgt * x.y;
    }
    ((float2*)out)[((size_t)b * SEQ + t) * 32 + l] = a;
}

// ============================================================
extern "C" void kernel_launch(void* const* d_in, const int* in_sizes, int n_in,
                              void* d_out, int out_size)
{
    const float* qk  = (const float*)d_in[0];
    const float* v   = (const float*)d_in[1];
    const float* rot = (const float*)d_in[2];

    cudaFuncSetAttribute(hash_kernel, cudaFuncAttributeMaxDynamicSharedMemorySize, 65536);
    cudaFuncSetAttribute(attn_kernel, cudaFuncAttributeMaxDynamicSharedMemorySize, SM_TOTAL);

    prep_kernel<<<(BATCH * SEQ) / 8, 256>>>(qk, v);
    hash_kernel<<<(BATCH * SEQ) / 128, 128, 65536>>>(qk, rot);
    sort_kernel<<<BATCH * NH, 128>>>();
    attn_kernel<<<dim3(NCHUNK / 2, BATCH), 256, SM_TOTAL>>>();
    combine_kernel<<<(BATCH * SEQ) / 8, 256>>>((float*)d_out);
}

// round 8
// speedup vs baseline: 2.7593x; 1.0042x over previous
#include <cuda_runtime.h>
#include <cuda_fp16.h>
#include <math.h>
#include <stdint.h>

#define BATCH 16
#define SEQ   4096
#define DIM   64
#define NH    8
#define NB    64
#define NCHUNK 512
#define SCALE 0.125f

// ---- fp16 mma.sync m16n8k16 + ldmatrix (baseline PTX) ----
__device__ __forceinline__ void mma_f16(float* c, uint32_t a0, uint32_t a1, uint32_t a2, uint32_t a3,
                                        uint32_t b0, uint32_t b1) {
    asm volatile("mma.sync.aligned.m16n8k16.row.col.f32.f16.f16.f32 "
                 "{%0,%1,%2,%3}, {%4,%5,%6,%7}, {%8,%9}, {%0,%1,%2,%3};"
                 : "+f"(c[0]), "+f"(c[1]), "+f"(c[2]), "+f"(c[3])
                 : "r"(a0), "r"(a1), "r"(a2), "r"(a3), "r"(b0), "r"(b1));
}
__device__ __forceinline__ void ldsm_x4(uint32_t addr, uint32_t& r0, uint32_t& r1, uint32_t& r2, uint32_t& r3) {
    asm volatile("ldmatrix.sync.aligned.m8n8.x4.shared.b16 {%0,%1,%2,%3}, [%4];"
                 : "=r"(r0), "=r"(r1), "=r"(r2), "=r"(r3) : "r"(addr));
}
__device__ __forceinline__ void ldsm_x4_t(uint32_t addr, uint32_t& r0, uint32_t& r1, uint32_t& r2, uint32_t& r3) {
    asm volatile("ldmatrix.sync.aligned.m8n8.x4.trans.shared.b16 {%0,%1,%2,%3}, [%4];"
                 : "=r"(r0), "=r"(r1), "=r"(r2), "=r"(r3) : "r"(addr));
}
__device__ __forceinline__ uint32_t smem_u32(const void* p) {
    uint32_t a;
    asm("{ .reg .u64 t; cvta.to.shared.u64 t, %1; cvt.u32.u64 %0, t; }" : "=r"(a) : "l"(p));
    return a;
}

// ---- packed f32x2 for hash kernel ----
__device__ __forceinline__ unsigned long long pk2(float x, float y) {
    unsigned long long r; asm("mov.b64 %0, {%1,%2};" : "=l"(r) : "f"(x), "f"(y)); return r;
}
__device__ __forceinline__ float2 upk2(unsigned long long a) {
    float2 r; asm("mov.b64 {%0,%1}, %2;" : "=f"(r.x), "=f"(r.y) : "l"(a)); return r;
}
#define FFMA2(d, a, b) asm("fma.rn.f32x2 %0, %1, %2, %0;" : "+l"(d) : "l"(a), "l"(b))

// ---- scratch ----
__device__ unsigned char g_buckets[BATCH * NH * SEQ];
__device__ int           g_st[BATCH * NH * SEQ];
__device__ __half        g_q16[(size_t)BATCH * SEQ * DIM];
__device__ __half        g_v16[(size_t)BATCH * SEQ * DIM];
__device__ float         g_inv[BATCH * SEQ];
__device__ __half        g_oh[(size_t)BATCH * NH * SEQ * DIM];
__device__ float         g_lse[BATCH * NH * SEQ];

// ============================================================
// Kernel 0: prep — fp16 copies + per-token inverse norm (warp/row)
// ============================================================
extern "C" __global__ void __launch_bounds__(256)
prep_kernel(const float* __restrict__ qk, const float* __restrict__ v)
{
    int row = blockIdx.x * 8 + (threadIdx.x >> 5);
    int l = threadIdx.x & 31;
    float2 xq = ((const float2*)(qk + (size_t)row * DIM))[l];
    float ss = xq.x * xq.x + xq.y * xq.y;
    #pragma unroll
    for (int o = 16; o >= 1; o >>= 1) ss += __shfl_xor_sync(0xffffffffu, ss, o);
    if (l == 0) g_inv[row] = SCALE / fmaxf(sqrtf(ss), 1e-12f);
    ((__half2*)(g_q16 + (size_t)row * DIM))[l] = __floats2half2_rn(xq.x, xq.y);
    float2 xv = ((const float2*)(v + (size_t)row * DIM))[l];
    ((__half2*)(g_v16 + (size_t)row * DIM))[l] = __floats2half2_rn(xv.x, xv.y);
}

// ============================================================
// Kernel 1: LSH hashing (FFMA2)
// ============================================================
extern "C" __global__ void __launch_bounds__(128)
hash_kernel(const float* __restrict__ qk, const float* __restrict__ rot)
{
    extern __shared__ float rot_s[];
    int tid = threadIdx.x;
    #pragma unroll
    for (int k = 0; k < 128; k++) rot_s[tid + k * 128] = rot[tid + k * 128];
    __syncthreads();

    int g = blockIdx.x * 128 + tid;
    int b = g >> 12, t = g & 4095;

    float q[64];
    const float4* qp = (const float4*)(qk + (size_t)g * 64);
    #pragma unroll
    for (int i = 0; i < 16; i++) {
        float4 x = qp[i];
        q[4*i] = x.x; q[4*i+1] = x.y; q[4*i+2] = x.z; q[4*i+3] = x.w;
    }

    for (int h = 0; h < NH; h++) {
        unsigned long long acc2[16];
        #pragma unroll
        for (int c = 0; c < 16; c++) acc2[c] = 0ull;
        #pragma unroll 4
        for (int f = 0; f < 64; f++) {
            unsigned long long q2 = pk2(q[f], q[f]);
            const ulonglong2* rp = (const ulonglong2*)(rot_s + f * 256 + h * 32);
            #pragma unroll
            for (int c4 = 0; c4 < 8; c4++) {
                ulonglong2 r2 = rp[c4];
                FFMA2(acc2[c4*2],   q2, r2.x);
                FFMA2(acc2[c4*2+1], q2, r2.y);
            }
        }
        float best = -1e30f; int bi = 0;
        #pragma unroll
        for (int c = 0; c < 16; c++) {
            float2 d = upk2(acc2[c]);
            if (d.x > best) { best = d.x; bi = 2*c; }
            if (d.y > best) { best = d.y; bi = 2*c+1; }
        }
        #pragma unroll
        for (int c = 0; c < 16; c++) {
            float2 d = upk2(acc2[c]);
            if (-d.x > best) { best = -d.x; bi = 32 + 2*c; }
            if (-d.y > best) { best = -d.y; bi = 32 + 2*c+1; }
        }
        g_buckets[(b * NH + h) * SEQ + t] = (unsigned char)bi;
    }
}

// ============================================================
// Kernel 2: stable counting sort per (batch, hash)
// ============================================================
extern "C" __global__ void __launch_bounds__(128)
sort_kernel()
{
    __shared__ int cnt[NB * 128];
    __shared__ int totals[NB];
    int tid = threadIdx.x;
    const unsigned char* bk = g_buckets + (size_t)blockIdx.x * SEQ;

    #pragma unroll
    for (int k = 0; k < NB; k++) cnt[k * 128 + tid] = 0;
    __syncthreads();

    int base = tid * 32;
    #pragma unroll
    for (int p = 0; p < 32; p++) { int c = bk[base + p]; cnt[c * 128 + tid]++; }
    __syncthreads();

    if (tid < NB) {
        int s = 0;
        for (int u = 0; u < 128; u++) s += cnt[tid * 128 + u];
        totals[tid] = s;
    }
    __syncthreads();
    if (tid == 0) {
        int r = 0;
        for (int c = 0; c < NB; c++) { int x = totals[c]; totals[c] = r; r += x; }
    }
    __syncthreads();
    if (tid < NB) {
        int run = totals[tid];
        for (int u = 0; u < 128; u++) { int x = cnt[tid * 128 + u]; cnt[tid * 128 + u] = run; run += x; }
    }
    __syncthreads();

    int* st = g_st + (size_t)blockIdx.x * SEQ;
    #pragma unroll
    for (int p = 0; p < 32; p++) {
        int pos = base + p;
        int c = bk[pos];
        int s = cnt[c * 128 + tid]++;
        st[s] = pos;
    }
}

// ============================================================
// Kernel 3: fp16 mma attention, chunk PAIR per block.
// Two-pass GEMM1 (register relief), P in registers,
// O staged through SMEM for coalesced 128B-row stores. 3 CTAs/SM.
// SMEM:
//   [0, 24576)      KQ tile: 192 rows x 128B, swizzle chunk^(row&7)
//                   (after GEMM1: per-warp O staging, warp w at w*2048)
//   [24576, 49152)  V tile: 192 rows x 128B
//   [49152, 49920)  kpos[192]
//   [49920, 50688)  inv[192]
// ============================================================
#define SM_V    24576
#define SM_KPOS 49152
#define SM_INV  49920
#define SM_TOTAL 50688

extern "C" __global__ void __launch_bounds__(256, 3)
attn_kernel()
{
    extern __shared__ char smem[];
    uint32_t sb = smem_u32(smem);
    int*   s_kpos = (int*)(smem + SM_KPOS);
    float* s_inv  = (float*)(smem + SM_INV);

    int tid = threadIdx.x;
    int w = tid >> 5, l = tid & 31;
    int pair = blockIdx.x, b = blockIdx.y;
    int c0 = 2 * pair;
    int pc = (c0 + NCHUNK - 1) & (NCHUNK - 1);
    int h = c0 >> 6;

    if (tid < 192) {
        int sel = tid >> 6;                          // 0=prev, 1=c0, 2=c1
        int ch = (sel == 0) ? pc : (c0 + sel - 1);
        int p = g_st[(b * NH + (ch >> 6)) * SEQ + (ch & 63) * 64 + (tid & 63)];
        s_kpos[tid] = p;
        s_inv[tid] = g_inv[b * SEQ + p];
    }
    __syncthreads();

    // gather 192 KQ rows + 192 V rows
    {
        int lane8 = tid & 7, rbase = tid >> 3;
        const __half* qsrc = g_q16 + (size_t)b * SEQ * DIM;
        const __half* vsrc = g_v16 + (size_t)b * SEQ * DIM;
        #pragma unroll
        for (int it = 0; it < 6; it++) {
            int j = rbase + 32 * it;                 // 0..191
            int p = s_kpos[j];
            uint32_t doff = j * 128 + ((lane8 ^ (j & 7)) << 4);
            *(uint4*)(smem + doff)        = *((const uint4*)(qsrc + (size_t)p * DIM) + lane8);
            *(uint4*)(smem + SM_V + doff) = *((const uint4*)(vsrc + (size_t)p * DIM) + lane8);
        }
    }
    __syncthreads();

    int r = l >> 2, q = l & 3;
    int base = (w < 4) ? 0 : 64;                     // key window start
    int qrow = 64 + 16 * w;

    // A fragments (Q) once
    uint32_t A[16];
    int arow = qrow + (l & 15);
    #pragma unroll
    for (int s = 0; s < 4; s++) {
        int ca = 2 * s + (l >> 4);
        ldsm_x4(sb + arow * 128 + ((ca ^ (arow & 7)) << 4), A[4*s], A[4*s+1], A[4*s+2], A[4*s+3]);
    }

    int row1 = qrow + r, row2 = row1 + 8;
    int qp1 = s_kpos[row1], qp2 = s_kpos[row2];
    float sum1 = 0.f, sum2 = 0.f;
    uint32_t pa[32];

    // GEMM1 in two 64-key passes (halves accumulator liveness)
    #pragma unroll
    for (int kh = 0; kh < 2; kh++) {
        float acc[8][4];
        #pragma unroll
        for (int j = 0; j < 8; j++)
            #pragma unroll
            for (int k = 0; k < 4; k++) acc[j][k] = 0.f;

        #pragma unroll
        for (int s = 0; s < 4; s++) {
            #pragma unroll
            for (int jp = 0; jp < 4; jp++) {
                int krow = base + 64 * kh + 16 * jp + (l & 15);
                int ca = 2 * s + (l >> 4);
                uint32_t b0, b1, b2, b3;
                ldsm_x4(sb + krow * 128 + ((ca ^ (krow & 7)) << 4), b0, b1, b2, b3);
                mma_f16(acc[2*jp],   A[4*s], A[4*s+1], A[4*s+2], A[4*s+3], b0, b2);
                mma_f16(acc[2*jp+1], A[4*s], A[4*s+1], A[4*s+2], A[4*s+3], b1, b3);
            }
        }

        // epilogue + pack this half
        #pragma unroll
        for (int j = 0; j < 8; j++) {
            int col = base + 64 * kh + 8 * j + 2 * q;
            float2 iv = *(const float2*)&s_inv[col];
            int2  kp = *(const int2*)&s_kpos[col];
            float e;
            e = (kp.x == qp1) ? 0.f : __expf(acc[j][0] * iv.x); acc[j][0] = e; sum1 += e;
            e = (kp.y == qp1) ? 0.f : __expf(acc[j][1] * iv.y); acc[j][1] = e; sum1 += e;
            e = (kp.x == qp2) ? 0.f : __expf(acc[j][2] * iv.x); acc[j][2] = e; sum2 += e;
            e = (kp.y == qp2) ? 0.f : __expf(acc[j][3] * iv.y); acc[j][3] = e; sum2 += e;
        }
        #pragma unroll
        for (int jp = 0; jp < 4; jp++) {
            __half2 t0 = __floats2half2_rn(acc[2*jp][0],   acc[2*jp][1]);
            __half2 t1 = __floats2half2_rn(acc[2*jp][2],   acc[2*jp][3]);
            __half2 t2 = __floats2half2_rn(acc[2*jp+1][0], acc[2*jp+1][1]);
            __half2 t3 = __floats2half2_rn(acc[2*jp+1][2], acc[2*jp+1][3]);
            pa[16*kh + 4*jp]     = *(uint32_t*)&t0;
            pa[16*kh + 4*jp + 1] = *(uint32_t*)&t1;
            pa[16*kh + 4*jp + 2] = *(uint32_t*)&t2;
            pa[16*kh + 4*jp + 3] = *(uint32_t*)&t3;
        }
    }
    sum1 += __shfl_xor_sync(0xffffffffu, sum1, 1);
    sum1 += __shfl_xor_sync(0xffffffffu, sum1, 2);
    sum2 += __shfl_xor_sync(0xffffffffu, sum2, 1);
    sum2 += __shfl_xor_sync(0xffffffffu, sum2, 2);

    __syncthreads();            // all warps done reading the KQ tile

    // GEMM2: O[16 x 64] per warp = P . V
    float o2[8][4];
    #pragma unroll
    for (int j = 0; j < 8; j++)
        #pragma unroll
        for (int k = 0; k < 4; k++) o2[j][k] = 0.f;

    #pragma unroll
    for (int s = 0; s < 8; s++) {
        int vrow = base + 16 * s + (l & 15);
        #pragma unroll
        for (int dp = 0; dp < 4; dp++) {
            int cv = 2 * dp + (l >> 4);
            uint32_t r0, r1, r2, r3;
            ldsm_x4_t(sb + SM_V + vrow * 128 + ((cv ^ (vrow & 7)) << 4), r0, r1, r2, r3);
            mma_f16(o2[2*dp],   pa[4*s], pa[4*s+1], pa[4*s+2], pa[4*s+3], r0, r1);
            mma_f16(o2[2*dp+1], pa[4*s], pa[4*s+1], pa[4*s+2], pa[4*s+3], r2, r3);
        }
    }

    float is1 = 1.f / sum1, is2 = 1.f / sum2;
    size_t obase = (size_t)(b * NH + h) * SEQ;
    if (q == 0) {
        g_lse[obase + qp1] = logf(sum1);
        g_lse[obase + qp2] = logf(sum2);
    }

    // stage O in warp-private SMEM slice (conflict-free swizzled STS)
    char* stg = smem + w * 2048;
    #pragma unroll
    for (int j = 0; j < 8; j++) {
        uint32_t off1 = r * 128       + ((j ^ (r & 7)) << 4) + 4 * q;
        uint32_t off2 = (r + 8) * 128 + ((j ^ ((r + 8) & 7)) << 4) + 4 * q;
        *(__half2*)(stg + off1) = __floats2half2_rn(o2[j][0] * is1, o2[j][1] * is1);
        *(__half2*)(stg + off2) = __floats2half2_rn(o2[j][2] * is2, o2[j][3] * is2);
    }
    __syncwarp();

    // read back 4 full rows per STG pass: lane = row (l>>3) within group, chunk = l&7
    #pragma unroll
    for (int i = 0; i < 4; i++) {
        int rl = i * 4 + (l >> 3);                   // 0..15 local row
        int cc = l & 7;
        uint4 val = *(uint4*)(stg + rl * 128 + ((cc ^ (rl & 7)) << 4));
        int p = s_kpos[qrow + rl];
        *((uint4*)(g_oh + (obase + p) * DIM) + cc) = val;
    }
}

// ============================================================
// Kernel 4: combine hash rounds (fp16 per-hash outputs)
// ============================================================
extern "C" __global__ void __launch_bounds__(256)
combine_kernel(float* __restrict__ out)
{
    int wid = blockIdx.x * 8 + (threadIdx.x >> 5);
    int l = threadIdx.x & 31;
    int b = wid >> 12, t = wid & 4095;

    float lse[NH];
    #pragma unroll
    for (int h = 0; h < NH; h++) lse[h] = g_lse[(b * NH + h) * SEQ + t];
    float m = lse[0];
    #pragma unroll
    for (int h = 1; h < NH; h++) m = fmaxf(m, lse[h]);
    float Z = 0.f;
    #pragma unroll
    for (int h = 0; h < NH; h++) Z += __expf(lse[h] - m);
    float iz = 1.f / Z;

    float2 a = make_float2(0.f, 0.f);
    #pragma unroll
    for (int h = 0; h < NH; h++) {
        float wgt = __expf(lse[h] - m) * iz;
        const __half2* row = (const __half2*)(g_oh + ((size_t)((b * NH + h) * SEQ) + t) * DIM);
        float2 x = __half22float2(row[l]);
        a.x += wgt * x.x;
        a.y += wgt * x.y;
    }
    ((float2*)out)[((size_t)b * SEQ + t) * 32 + l] = a;
}

// ============================================================
extern "C" void kernel_launch(void* const* d_in, const int* in_sizes, int n_in,
                              void* d_out, int out_size)
{
    const float* qk  = (const float*)d_in[0];
    const float* v   = (const float*)d_in[1];
    const float* rot = (const float*)d_in[2];

    cudaFuncSetAttribute(hash_kernel, cudaFuncAttributeMaxDynamicSharedMemorySize, 65536);
    cudaFuncSetAttribute(attn_kernel, cudaFuncAttributeMaxDynamicSharedMemorySize, SM_TOTAL);

    prep_kernel<<<(BATCH * SEQ) / 8, 256>>>(qk, v);
    hash_kernel<<<(BATCH * SEQ) / 128, 128, 65536>>>(qk, rot);
    sort_kernel<<<BATCH * NH, 128>>>();
    attn_kernel<<<dim3(NCHUNK / 2, BATCH), 256, SM_TOTAL>>>();
    combine_kernel<<<(BATCH * SEQ) / 8, 256>>>((float*)d_out);
}

// round 9
// speedup vs baseline: 2.8457x; 1.0313x over previous
#include <cuda_runtime.h>
#include <cuda_fp16.h>
#include <math.h>
#include <stdint.h>

#define BATCH 16
#define SEQ   4096
#define DIM   64
#define NH    8
#define NB    64
#define NCHUNK 512
#define SCALE 0.125f

// ---- fp16 mma.sync m16n8k16 + ldmatrix (baseline PTX) ----
__device__ __forceinline__ void mma_f16(float* c, uint32_t a0, uint32_t a1, uint32_t a2, uint32_t a3,
                                        uint32_t b0, uint32_t b1) {
    asm volatile("mma.sync.aligned.m16n8k16.row.col.f32.f16.f16.f32 "
                 "{%0,%1,%2,%3}, {%4,%5,%6,%7}, {%8,%9}, {%0,%1,%2,%3};"
                 : "+f"(c[0]), "+f"(c[1]), "+f"(c[2]), "+f"(c[3])
                 : "r"(a0), "r"(a1), "r"(a2), "r"(a3), "r"(b0), "r"(b1));
}
__device__ __forceinline__ void ldsm_x4(uint32_t addr, uint32_t& r0, uint32_t& r1, uint32_t& r2, uint32_t& r3) {
    asm volatile("ldmatrix.sync.aligned.m8n8.x4.shared.b16 {%0,%1,%2,%3}, [%4];"
                 : "=r"(r0), "=r"(r1), "=r"(r2), "=r"(r3) : "r"(addr));
}
__device__ __forceinline__ void ldsm_x4_t(uint32_t addr, uint32_t& r0, uint32_t& r1, uint32_t& r2, uint32_t& r3) {
    asm volatile("ldmatrix.sync.aligned.m8n8.x4.trans.shared.b16 {%0,%1,%2,%3}, [%4];"
                 : "=r"(r0), "=r"(r1), "=r"(r2), "=r"(r3) : "r"(addr));
}
__device__ __forceinline__ uint32_t smem_u32(const void* p) {
    uint32_t a;
    asm("{ .reg .u64 t; cvta.to.shared.u64 t, %1; cvt.u32.u64 %0, t; }" : "=r"(a) : "l"(p));
    return a;
}
// ---- async bulk copy (sm_90 baseline) ----
__device__ __forceinline__ void bulk_cp(uint32_t dst, const void* src, uint32_t bytes, uint32_t mbar) {
    uint64_t g;
    asm("cvta.to.global.u64 %0, %1;" : "=l"(g) : "l"(src));
    asm volatile("cp.async.bulk.shared::cluster.global.mbarrier::complete_tx::bytes [%0], [%1], %2, [%3];"
                 :: "r"(dst), "l"(g), "r"(bytes), "r"(mbar) : "memory");
}
#define MBARRIER_INIT(mb, n) \
    asm volatile("mbarrier.init.shared.b64 [%0], %1;" :: "r"((uint32_t)(mb)), "r"((uint32_t)(n)) : "memory")
#define MBARRIER_EXPECT_TX(mb, tx) \
    asm volatile("mbarrier.arrive.expect_tx.shared.b64 _, [%0], %1;" :: "r"((uint32_t)(mb)), "r"((uint32_t)(tx)) : "memory")
#define MBARRIER_WAIT(mb, ph) do { \
    uint32_t _m = (uint32_t)(mb), _p = (uint32_t)(ph), _d; \
    asm volatile("{\n\t.reg .pred p;\n\tmbarrier.try_wait.parity.acquire.cta.shared::cta.b64 p, [%1], %2;\n\tselp.b32 %0,1,0,p;\n\t}" \
                 : "=r"(_d) : "r"(_m), "r"(_p) : "memory"); \
    if (!_d) { \
        asm volatile("{\n\t.reg .pred P1;\n\tWL_%=:\n\tmbarrier.try_wait.parity.acquire.cta.shared::cta.b64 P1, [%0], %1, 0x989680;\n\t@P1 bra.uni WD_%=;\n\tbra.uni WL_%=;\n\tWD_%=:\n\t}" \
                     :: "r"(_m), "r"(_p) : "memory"); \
    } } while (0)

// ---- packed f32x2 for hash kernel ----
__device__ __forceinline__ unsigned long long pk2(float x, float y) {
    unsigned long long r; asm("mov.b64 %0, {%1,%2};" : "=l"(r) : "f"(x), "f"(y)); return r;
}
__device__ __forceinline__ float2 upk2(unsigned long long a) {
    float2 r; asm("mov.b64 {%0,%1}, %2;" : "=f"(r.x), "=f"(r.y) : "l"(a)); return r;
}
#define FFMA2(d, a, b) asm("fma.rn.f32x2 %0, %1, %2, %0;" : "+l"(d) : "l"(a), "l"(b))

// ---- scratch ----
__device__ unsigned char g_buckets[BATCH * NH * SEQ];
__device__ int           g_st[BATCH * NH * SEQ];
__device__ __half        g_q16[(size_t)BATCH * SEQ * DIM];
__device__ __half        g_v16[(size_t)BATCH * SEQ * DIM];
__device__ float         g_inv[BATCH * SEQ];
__device__ __half        g_oh[(size_t)BATCH * NH * SEQ * DIM];
__device__ float         g_lse[BATCH * NH * SEQ];

// ============================================================
// Kernel 1: LSH hashing (FFMA2) + fused fp16 prep of qk & v + inv norm
// ============================================================
extern "C" __global__ void __launch_bounds__(128)
hash_kernel(const float* __restrict__ qk, const float* __restrict__ v, const float* __restrict__ rot)
{
    extern __shared__ float rot_s[];
    int tid = threadIdx.x;
    #pragma unroll
    for (int k = 0; k < 128; k++) rot_s[tid + k * 128] = rot[tid + k * 128];
    __syncthreads();

    int g = blockIdx.x * 128 + tid;
    int b = g >> 12, t = g & 4095;

    // load q row, accumulate norm, convert to fp16
    float q[64];
    float ss = 0.f;
    const float4* qp = (const float4*)(qk + (size_t)g * 64);
    uint4* q16o = (uint4*)(g_q16 + (size_t)g * 64);
    #pragma unroll
    for (int i = 0; i < 8; i++) {
        float4 x = qp[2*i], y = qp[2*i+1];
        q[8*i]   = x.x; q[8*i+1] = x.y; q[8*i+2] = x.z; q[8*i+3] = x.w;
        q[8*i+4] = y.x; q[8*i+5] = y.y; q[8*i+6] = y.z; q[8*i+7] = y.w;
        ss += x.x*x.x + x.y*x.y + x.z*x.z + x.w*x.w;
        ss += y.x*y.x + y.y*y.y + y.z*y.z + y.w*y.w;
        __half2 h0 = __floats2half2_rn(x.x, x.y), h1 = __floats2half2_rn(x.z, x.w);
        __half2 h2 = __floats2half2_rn(y.x, y.y), h3 = __floats2half2_rn(y.z, y.w);
        q16o[i] = make_uint4(*(uint32_t*)&h0, *(uint32_t*)&h1, *(uint32_t*)&h2, *(uint32_t*)&h3);
    }
    g_inv[g] = SCALE / fmaxf(sqrtf(ss), 1e-12f);

    // convert v row to fp16
    {
        const float4* vp = (const float4*)(v + (size_t)g * 64);
        uint4* v16o = (uint4*)(g_v16 + (size_t)g * 64);
        #pragma unroll
        for (int i = 0; i < 8; i++) {
            float4 x = vp[2*i], y = vp[2*i+1];
            __half2 h0 = __floats2half2_rn(x.x, x.y), h1 = __floats2half2_rn(x.z, x.w);
            __half2 h2 = __floats2half2_rn(y.x, y.y), h3 = __floats2half2_rn(y.z, y.w);
            v16o[i] = make_uint4(*(uint32_t*)&h0, *(uint32_t*)&h1, *(uint32_t*)&h2, *(uint32_t*)&h3);
        }
    }

    for (int h = 0; h < NH; h++) {
        unsigned long long acc2[16];
        #pragma unroll
        for (int c = 0; c < 16; c++) acc2[c] = 0ull;
        #pragma unroll 4
        for (int f = 0; f < 64; f++) {
            unsigned long long q2 = pk2(q[f], q[f]);
            const ulonglong2* rp = (const ulonglong2*)(rot_s + f * 256 + h * 32);
            #pragma unroll
            for (int c4 = 0; c4 < 8; c4++) {
                ulonglong2 r2 = rp[c4];
                FFMA2(acc2[c4*2],   q2, r2.x);
                FFMA2(acc2[c4*2+1], q2, r2.y);
            }
        }
        float best = -1e30f; int bi = 0;
        #pragma unroll
        for (int c = 0; c < 16; c++) {
            float2 d = upk2(acc2[c]);
            if (d.x > best) { best = d.x; bi = 2*c; }
            if (d.y > best) { best = d.y; bi = 2*c+1; }
        }
        #pragma unroll
        for (int c = 0; c < 16; c++) {
            float2 d = upk2(acc2[c]);
            if (-d.x > best) { best = -d.x; bi = 32 + 2*c; }
            if (-d.y > best) { best = -d.y; bi = 32 + 2*c+1; }
        }
        g_buckets[(b * NH + h) * SEQ + t] = (unsigned char)bi;
    }
}

// ============================================================
// Kernel 2: stable counting sort per (batch, hash)
// ============================================================
extern "C" __global__ void __launch_bounds__(128)
sort_kernel()
{
    __shared__ int cnt[NB * 128];
    __shared__ int totals[NB];
    int tid = threadIdx.x;
    const unsigned char* bk = g_buckets + (size_t)blockIdx.x * SEQ;

    #pragma unroll
    for (int k = 0; k < NB; k++) cnt[k * 128 + tid] = 0;
    __syncthreads();

    int base = tid * 32;
    #pragma unroll
    for (int p = 0; p < 32; p++) { int c = bk[base + p]; cnt[c * 128 + tid]++; }
    __syncthreads();

    if (tid < NB) {
        int s = 0;
        for (int u = 0; u < 128; u++) s += cnt[tid * 128 + u];
        totals[tid] = s;
    }
    __syncthreads();
    if (tid == 0) {
        int r = 0;
        for (int c = 0; c < NB; c++) { int x = totals[c]; totals[c] = r; r += x; }
    }
    __syncthreads();
    if (tid < NB) {
        int run = totals[tid];
        for (int u = 0; u < 128; u++) { int x = cnt[tid * 128 + u]; cnt[tid * 128 + u] = run; run += x; }
    }
    __syncthreads();

    int* st = g_st + (size_t)blockIdx.x * SEQ;
    #pragma unroll
    for (int p = 0; p < 32; p++) {
        int pos = base + p;
        int c = bk[pos];
        int s = cnt[c * 128 + tid]++;
        st[s] = pos;
    }
}

// ============================================================
// Kernel 3: fp16 mma attention, chunk PAIR per block.
// Gather via cp.async.bulk (128B rows -> 144B-stride SMEM, pad swizzle:
// 16B-granule bank of (row j, chunk c) = (j + c) mod 8 -> ldmatrix conflict-free).
// Two-pass GEMM1, P in registers, O staged for coalesced stores. 3 CTAs/SM.
// SMEM:
//   [0, 27648)      KQ tile: 192 rows x 144B (O staging reuses: warp w at w*2304)
//   [27648, 55296)  V tile: 192 rows x 144B
//   [55296, 56064)  kpos[192]
//   [56064, 56832)  inv[192]
//   [56832, 56840)  mbarrier
// ============================================================
#define KQSTR   144
#define SM_V    27648
#define SM_KPOS 55296
#define SM_INV  56064
#define SM_MB   56832
#define SM_TOTAL 56840

extern "C" __global__ void __launch_bounds__(256, 3)
attn_kernel()
{
    extern __shared__ char smem[];
    uint32_t sb = smem_u32(smem);
    int*   s_kpos = (int*)(smem + SM_KPOS);
    float* s_inv  = (float*)(smem + SM_INV);

    int tid = threadIdx.x;
    int w = tid >> 5, l = tid & 31;
    int pair = blockIdx.x, b = blockIdx.y;
    int c0 = 2 * pair;
    int pc = (c0 + NCHUNK - 1) & (NCHUNK - 1);
    int h = c0 >> 6;

    if (tid == 0) MBARRIER_INIT(sb + SM_MB, 1);
    __syncthreads();

    if (tid < 192) {
        int sel = tid >> 6;                          // 0=prev, 1=c0, 2=c1
        int ch = (sel == 0) ? pc : (c0 + sel - 1);
        int p = g_st[(b * NH + (ch >> 6)) * SEQ + (ch & 63) * 64 + (tid & 63)];
        s_kpos[tid] = p;
        s_inv[tid] = g_inv[b * SEQ + p];
        const __half* qsrc = g_q16 + ((size_t)b * SEQ + p) * DIM;
        const __half* vsrc = g_v16 + ((size_t)b * SEQ + p) * DIM;
        bulk_cp(sb + tid * KQSTR,        qsrc, 128, sb + SM_MB);
        bulk_cp(sb + SM_V + tid * KQSTR, vsrc, 128, sb + SM_MB);
    }
    if (tid == 0) MBARRIER_EXPECT_TX(sb + SM_MB, 384 * 128);
    __syncthreads();                                 // kpos/inv visibility
    MBARRIER_WAIT(sb + SM_MB, 0);

    int r = l >> 2, q = l & 3;
    int base = (w < 4) ? 0 : 64;                     // key window start
    int qrow = 64 + 16 * w;

    // A fragments (Q) once
    uint32_t A[16];
    int arow = qrow + (l & 15);
    #pragma unroll
    for (int s = 0; s < 4; s++) {
        int ca = 2 * s + (l >> 4);
        ldsm_x4(sb + arow * KQSTR + ca * 16, A[4*s], A[4*s+1], A[4*s+2], A[4*s+3]);
    }

    int row1 = qrow + r, row2 = row1 + 8;
    int qp1 = s_kpos[row1], qp2 = s_kpos[row2];
    float sum1 = 0.f, sum2 = 0.f;
    uint32_t pa[32];

    // GEMM1 in two 64-key passes
    #pragma unroll
    for (int kh = 0; kh < 2; kh++) {
        float acc[8][4];
        #pragma unroll
        for (int j = 0; j < 8; j++)
            #pragma unroll
            for (int k = 0; k < 4; k++) acc[j][k] = 0.f;

        #pragma unroll
        for (int s = 0; s < 4; s++) {
            #pragma unroll
            for (int jp = 0; jp < 4; jp++) {
                int krow = base + 64 * kh + 16 * jp + (l & 15);
                int ca = 2 * s + (l >> 4);
                uint32_t b0, b1, b2, b3;
                ldsm_x4(sb + krow * KQSTR + ca * 16, b0, b1, b2, b3);
                mma_f16(acc[2*jp],   A[4*s], A[4*s+1], A[4*s+2], A[4*s+3], b0, b2);
                mma_f16(acc[2*jp+1], A[4*s], A[4*s+1], A[4*s+2], A[4*s+3], b1, b3);
            }
        }

        #pragma unroll
        for (int j = 0; j < 8; j++) {
            int col = base + 64 * kh + 8 * j + 2 * q;
            float2 iv = *(const float2*)&s_inv[col];
            int2  kp = *(const int2*)&s_kpos[col];
            float e;
            e = (kp.x == qp1) ? 0.f : __expf(acc[j][0] * iv.x); acc[j][0] = e; sum1 += e;
            e = (kp.y == qp1) ? 0.f : __expf(acc[j][1] * iv.y); acc[j][1] = e; sum1 += e;
            e = (kp.x == qp2) ? 0.f : __expf(acc[j][2] * iv.x); acc[j][2] = e; sum2 += e;
            e = (kp.y == qp2) ? 0.f : __expf(acc[j][3] * iv.y); acc[j][3] = e; sum2 += e;
        }
        #pragma unroll
        for (int jp = 0; jp < 4; jp++) {
            __half2 t0 = __floats2half2_rn(acc[2*jp][0],   acc[2*jp][1]);
            __half2 t1 = __floats2half2_rn(acc[2*jp][2],   acc[2*jp][3]);
            __half2 t2 = __floats2half2_rn(acc[2*jp+1][0], acc[2*jp+1][1]);
            __half2 t3 = __floats2half2_rn(acc[2*jp+1][2], acc[2*jp+1][3]);
            pa[16*kh + 4*jp]     = *(uint32_t*)&t0;
            pa[16*kh + 4*jp + 1] = *(uint32_t*)&t1;
            pa[16*kh + 4*jp + 2] = *(uint32_t*)&t2;
            pa[16*kh + 4*jp + 3] = *(uint32_t*)&t3;
        }
    }
    sum1 += __shfl_xor_sync(0xffffffffu, sum1, 1);
    sum1 += __shfl_xor_sync(0xffffffffu, sum1, 2);
    sum2 += __shfl_xor_sync(0xffffffffu, sum2, 1);
    sum2 += __shfl_xor_sync(0xffffffffu, sum2, 2);

    __syncthreads();            // all warps done reading the KQ tile

    // GEMM2: O[16 x 64] per warp = P . V
    float o2[8][4];
    #pragma unroll
    for (int j = 0; j < 8; j++)
        #pragma unroll
        for (int k = 0; k < 4; k++) o2[j][k] = 0.f;

    #pragma unroll
    for (int s = 0; s < 8; s++) {
        int vrow = base + 16 * s + (l & 15);
        #pragma unroll
        for (int dp = 0; dp < 4; dp++) {
            int cv = 2 * dp + (l >> 4);
            uint32_t r0, r1, r2, r3;
            ldsm_x4_t(sb + SM_V + vrow * KQSTR + cv * 16, r0, r1, r2, r3);
            mma_f16(o2[2*dp],   pa[4*s], pa[4*s+1], pa[4*s+2], pa[4*s+3], r0, r1);
            mma_f16(o2[2*dp+1], pa[4*s], pa[4*s+1], pa[4*s+2], pa[4*s+3], r2, r3);
        }
    }

    float is1 = 1.f / sum1, is2 = 1.f / sum2;
    size_t obase = (size_t)(b * NH + h) * SEQ;
    if (q == 0) {
        g_lse[obase + qp1] = logf(sum1);
        g_lse[obase + qp2] = logf(sum2);
    }

    // stage O in warp-private SMEM slice (144B-stride rows, conflict-free)
    char* stg = smem + w * (16 * KQSTR);
    #pragma unroll
    for (int j = 0; j < 8; j++) {
        *(__half2*)(stg + r * KQSTR       + j * 16 + 4 * q) = __floats2half2_rn(o2[j][0] * is1, o2[j][1] * is1);
        *(__half2*)(stg + (r + 8) * KQSTR + j * 16 + 4 * q) = __floats2half2_rn(o2[j][2] * is2, o2[j][3] * is2);
    }
    __syncwarp();

    #pragma unroll
    for (int i = 0; i < 4; i++) {
        int rl = i * 4 + (l >> 3);                   // 0..15 local row
        int cc = l & 7;
        uint4 val = *(uint4*)(stg + rl * KQSTR + cc * 16);
        int p = s_kpos[qrow + rl];
        *((uint4*)(g_oh + (obase + p) * DIM) + cc) = val;
    }
}

// ============================================================
// Kernel 4: combine hash rounds (fp16 per-hash outputs)
// ============================================================
extern "C" __global__ void __launch_bounds__(256)
combine_kernel(float* __restrict__ out)
{
    int wid = blockIdx.x * 8 + (threadIdx.x >> 5);
    int l = threadIdx.x & 31;
    int b = wid >> 12, t = wid & 4095;

    float lse[NH];
    #pragma unroll
    for (int h = 0; h < NH; h++) lse[h] = g_lse[(b * NH + h) * SEQ + t];
    float m = lse[0];
    #pragma unroll
    for (int h = 1; h < NH; h++) m = fmaxf(m, lse[h]);
    float Z = 0.f;
    #pragma unroll
    for (int h = 0; h < NH; h++) Z += __expf(lse[h] - m);
    float iz = 1.f / Z;

    float2 a = make_float2(0.f, 0.f);
    #pragma unroll
    for (int h = 0; h < NH; h++) {
        float wgt = __expf(lse[h] - m) * iz;
        const __half2* row = (const __half2*)(g_oh + ((size_t)((b * NH + h) * SEQ) + t) * DIM);
        float2 x = __half22float2(row[l]);
        a.x += wgt * x.x;
        a.y += wgt * x.y;
    }
    ((float2*)out)[((size_t)b * SEQ + t) * 32 + l] = a;
}

// ============================================================
extern "C" void kernel_launch(void* const* d_in, const int* in_sizes, int n_in,
                              void* d_out, int out_size)
{
    const float* qk  = (const float*)d_in[0];
    const float* v   = (const float*)d_in[1];
    const float* rot = (const float*)d_in[2];

    cudaFuncSetAttribute(hash_kernel, cudaFuncAttributeMaxDynamicSharedMemorySize, 65536);
    cudaFuncSetAttribute(attn_kernel, cudaFuncAttributeMaxDynamicSharedMemorySize, SM_TOTAL);

    hash_kernel<<<(BATCH * SEQ) / 128, 128, 65536>>>(qk, v, rot);
    sort_kernel<<<BATCH * NH, 128>>>();
    attn_kernel<<<dim3(NCHUNK / 2, BATCH), 256, SM_TOTAL>>>();
    combine_kernel<<<(BATCH * SEQ) / 8, 256>>>((float*)d_out);
}